// round 5
// baseline (speedup 1.0000x reference)
#include <cuda_runtime.h>

#define VOCAB  32000
#define EMBED  512
#define HIDDEN 512
#define BATCH  64
#define TSTEPS 64

// -------- persistent scratch (no allocs allowed) --------
__device__ float g_h[2][BATCH * HIDDEN];
__device__ float g_c[BATCH * HIDDEN];
__device__ unsigned long long g_amax[TSTEPS * BATCH];

// monotone float -> uint mapping for atomicMax-based argmax
__device__ __forceinline__ unsigned int ford(float f) {
    unsigned int u = __float_as_uint(f);
    return (u & 0x80000000u) ? ~u : (u | 0x80000000u);
}

// ---------------- init: copy initial state, zero argmax slots ----------------
__global__ void init_kernel(const float* __restrict__ hidden,
                            const float* __restrict__ cell) {
    int i = blockIdx.x * blockDim.x + threadIdx.x;
    if (i < BATCH * HIDDEN) {
        g_h[0][i] = hidden[i];
        g_c[i]    = cell[i];
    }
    if (i < TSTEPS * BATCH) g_amax[i] = 0ull;
}

// ---------------- LSTM step: gates GEMM + cell update ----------------
// grid = 128 CTAs, each owns 4 hidden units (16 gate rows) x all 64 batches.
// thread (m = tid&63, q = tid>>6) computes i,f,g,o for (batch m, unit j0+q)
// and performs the cell update in-register.
__global__ __launch_bounds__(256) void lstm_step_kernel(
    const float* __restrict__ embedding,
    const float* __restrict__ w_ih,
    const float* __restrict__ w_hh,
    const float* __restrict__ b_ih,
    const float* __restrict__ b_hh,
    const int*   __restrict__ start_tok,
    int t)
{
    __shared__ float As[128][64];   // [k][b]   32 KB
    __shared__ float Ws[128][16];   // [k][r']   8 KB ; r' = q*4 + gate
    __shared__ int   toks[BATCH];

    const int tid = threadIdx.x;
    const int j0  = blockIdx.x * 4;
    const int rb  = t & 1;          // h buffer to read
    const int wb  = rb ^ 1;         // h buffer to write

    if (tid < BATCH) {
        if (t == 0) toks[tid] = *start_tok;
        else {
            unsigned long long key = g_amax[(t - 1) * BATCH + tid];
            toks[tid] = (int)(~((unsigned int)(key & 0xFFFFFFFFull)));
        }
    }
    __syncthreads();

    const int m = tid & 63;
    const int q = tid >> 6;         // 0..3 : unit within CTA
    float acc0 = 0.f, acc1 = 0.f, acc2 = 0.f, acc3 = 0.f;

    for (int kc = 0; kc < 8; kc++) {
        const int kbase = kc * 128;
        // ---- load activation chunk A[b][kbase..kbase+127] -> As[k][b]
        {
            const int b   = tid >> 2;
            const int klo = (tid & 3) * 32;
            const float* src = (kbase < EMBED)
                ? embedding + (size_t)toks[b] * EMBED + kbase + klo
                : g_h[rb] + b * HIDDEN + (kbase - EMBED) + klo;
            #pragma unroll
            for (int i = 0; i < 8; i++) {
                float4 v = *(const float4*)(src + i * 4);
                int k = klo + i * 4;
                As[k][b] = v.x; As[k+1][b] = v.y; As[k+2][b] = v.z; As[k+3][b] = v.w;
            }
        }
        // ---- load weight chunk: 16 gate rows x 128 k -> Ws[k][r']
        {
            const int rp  = tid >> 4;            // r' = 0..15
            const int klo = (tid & 15) * 8;
            const int R   = (rp & 3) * HIDDEN + j0 + (rp >> 2); // gate*512 + unit
            const float* src = (kbase < EMBED)
                ? w_ih + (size_t)R * EMBED + kbase + klo
                : w_hh + (size_t)R * HIDDEN + (kbase - EMBED) + klo;
            #pragma unroll
            for (int i = 0; i < 2; i++) {
                float4 v = *(const float4*)(src + i * 4);
                int k = klo + i * 4;
                Ws[k][rp] = v.x; Ws[k+1][rp] = v.y; Ws[k+2][rp] = v.z; Ws[k+3][rp] = v.w;
            }
        }
        __syncthreads();

        #pragma unroll 16
        for (int k = 0; k < 128; k++) {
            float  a = As[k][m];
            float4 w = *(const float4*)&Ws[k][q * 4];
            acc0 += a * w.x; acc1 += a * w.y; acc2 += a * w.z; acc3 += a * w.w;
        }
        __syncthreads();
    }

    // ---- biases + activations + cell update
    const int unit = j0 + q;
    acc0 += b_ih[0 * HIDDEN + unit] + b_hh[0 * HIDDEN + unit];
    acc1 += b_ih[1 * HIDDEN + unit] + b_hh[1 * HIDDEN + unit];
    acc2 += b_ih[2 * HIDDEN + unit] + b_hh[2 * HIDDEN + unit];
    acc3 += b_ih[3 * HIDDEN + unit] + b_hh[3 * HIDDEN + unit];

    float ig = 1.f / (1.f + expf(-acc0));
    float fg = 1.f / (1.f + expf(-acc1));
    float gg = tanhf(acc2);
    float og = 1.f / (1.f + expf(-acc3));

    const int ci = m * HIDDEN + unit;
    float c = fg * g_c[ci] + ig * gg;
    g_c[ci] = c;
    g_h[wb][ci] = og * tanhf(c);
}

// ---------------- fc: logits GEMM + write + fused argmax ----------------
// grid = 250 CTAs, tile [64 m x 128 n], K=512 in chunks of 64.
// thread (tx = tid&15 -> 8 n, ty = tid>>4 -> 4 m), 32 accumulators.
__global__ __launch_bounds__(256) void fc_kernel(
    const float* __restrict__ fc_w,
    const float* __restrict__ fc_b,
    float* __restrict__ out,
    int t)
{
    __shared__ float Hs[64][64];    // [k][b]   16 KB
    __shared__ float Ws[64][128];   // [k][n]   32 KB  (total exactly 48 KB)

    const int tid = threadIdx.x;
    const int n0  = blockIdx.x * 128;
    const int hb  = (t & 1) ^ 1;    // h buffer written by this step's lstm
    const int tx  = tid & 15;
    const int ty  = tid >> 4;

    float acc[4][8];
    #pragma unroll
    for (int i = 0; i < 4; i++)
        #pragma unroll
        for (int j = 0; j < 8; j++) acc[i][j] = 0.f;

    for (int kc = 0; kc < 8; kc++) {
        const int kbase = kc * 64;
        // ---- Hs: h[b][kbase..kbase+63] -> Hs[k][b]
        {
            const int b   = tid >> 2;
            const int klo = (tid & 3) * 16;
            const float* src = g_h[hb] + b * HIDDEN + kbase + klo;
            #pragma unroll
            for (int i = 0; i < 4; i++) {
                float4 v = *(const float4*)(src + i * 4);
                int k = klo + i * 4;
                Hs[k][b] = v.x; Hs[k+1][b] = v.y; Hs[k+2][b] = v.z; Hs[k+3][b] = v.w;
            }
        }
        // ---- Ws: fc_w[n0+n][kbase..kbase+63] -> Ws[k][n]
        {
            const int n   = tid >> 1;
            const int klo = (tid & 1) * 32;
            const float* src = fc_w + (size_t)(n0 + n) * HIDDEN + kbase + klo;
            #pragma unroll
            for (int i = 0; i < 8; i++) {
                float4 v = *(const float4*)(src + i * 4);
                int k = klo + i * 4;
                Ws[k][n] = v.x; Ws[k+1][n] = v.y; Ws[k+2][n] = v.z; Ws[k+3][n] = v.w;
            }
        }
        __syncthreads();

        #pragma unroll 8
        for (int k = 0; k < 64; k++) {
            float4 a  = *(const float4*)&Hs[k][ty * 4];
            float4 w0 = *(const float4*)&Ws[k][tx * 8];
            float4 w1 = *(const float4*)&Ws[k][tx * 8 + 4];
            float av[4] = {a.x, a.y, a.z, a.w};
            float wv[8] = {w0.x, w0.y, w0.z, w0.w, w1.x, w1.y, w1.z, w1.w};
            #pragma unroll
            for (int mi = 0; mi < 4; mi++)
                #pragma unroll
                for (int ni = 0; ni < 8; ni++)
                    acc[mi][ni] += av[mi] * wv[ni];
        }
        __syncthreads();
    }

    // ---- bias
    float4 b0 = *(const float4*)(fc_b + n0 + tx * 8);
    float4 b1 = *(const float4*)(fc_b + n0 + tx * 8 + 4);
    float bv[8] = {b0.x, b0.y, b0.z, b0.w, b1.x, b1.y, b1.z, b1.w};
    #pragma unroll
    for (int mi = 0; mi < 4; mi++)
        #pragma unroll
        for (int ni = 0; ni < 8; ni++)
            acc[mi][ni] += bv[ni];

    // ---- write logits: out[b][t][v]
    #pragma unroll
    for (int mi = 0; mi < 4; mi++) {
        const int m = ty * 4 + mi;
        float* dst = out + (size_t)m * TSTEPS * VOCAB + (size_t)t * VOCAB + n0 + tx * 8;
        *(float4*)(dst)     = make_float4(acc[mi][0], acc[mi][1], acc[mi][2], acc[mi][3]);
        *(float4*)(dst + 4) = make_float4(acc[mi][4], acc[mi][5], acc[mi][6], acc[mi][7]);
    }

    // ---- fused argmax: local -> 16-lane shfl reduce -> global atomicMax
    float bestv[4];
    int   bestn[4];
    #pragma unroll
    for (int mi = 0; mi < 4; mi++) {
        bestv[mi] = acc[mi][0];
        bestn[mi] = n0 + tx * 8;
        #pragma unroll
        for (int ni = 1; ni < 8; ni++) {
            int n = n0 + tx * 8 + ni;
            float v = acc[mi][ni];
            if (v > bestv[mi] || (v == bestv[mi] && n < bestn[mi])) {
                bestv[mi] = v; bestn[mi] = n;
            }
        }
    }
    #pragma unroll
    for (int off = 8; off > 0; off >>= 1) {
        #pragma unroll
        for (int mi = 0; mi < 4; mi++) {
            float ov = __shfl_xor_sync(0xffffffffu, bestv[mi], off);
            int   on = __shfl_xor_sync(0xffffffffu, bestn[mi], off);
            if (ov > bestv[mi] || (ov == bestv[mi] && on < bestn[mi])) {
                bestv[mi] = ov; bestn[mi] = on;
            }
        }
    }
    if (tx == 0) {
        #pragma unroll
        for (int mi = 0; mi < 4; mi++) {
            const int m = ty * 4 + mi;
            unsigned long long key =
                ((unsigned long long)ford(bestv[mi]) << 32) |
                (unsigned long long)(unsigned int)(~bestn[mi]);
            atomicMax(&g_amax[t * BATCH + m], key);
        }
    }
}

// ---------------- launch ----------------
extern "C" void kernel_launch(void* const* d_in, const int* in_sizes, int n_in,
                              void* d_out, int out_size) {
    const float* hidden    = (const float*)d_in[0];
    const float* cell      = (const float*)d_in[1];
    /* d_in[2] = max_length (compile-time TSTEPS) */
    const int*   start_tok = (const int*)d_in[3];
    const float* embedding = (const float*)d_in[4];
    const float* w_ih      = (const float*)d_in[5];
    const float* w_hh      = (const float*)d_in[6];
    const float* b_ih      = (const float*)d_in[7];
    const float* b_hh      = (const float*)d_in[8];
    const float* fc_w      = (const float*)d_in[9];
    const float* fc_b      = (const float*)d_in[10];
    float* out = (float*)d_out;

    init_kernel<<<128, 256>>>(hidden, cell);
    for (int t = 0; t < TSTEPS; t++) {
        lstm_step_kernel<<<128, 256>>>(embedding, w_ih, w_hh, b_ih, b_hh, start_tok, t);
        fc_kernel<<<VOCAB / 128, 256>>>(fc_w, fc_b, out, t);
    }
}

// round 8
// speedup vs baseline: 1.7060x; 1.7060x over previous
#include <cuda_runtime.h>
#include <cuda_bf16.h>
#include <cstdint>

#define VOCAB  32000
#define EMBED  512
#define HIDDEN 512
#define BATCH  64
#define TSTEPS 64

// -------- persistent scratch (no allocs allowed) --------
__device__ float g_h[2][BATCH * HIDDEN];
__device__ float g_c[BATCH * HIDDEN];
__device__ unsigned long long g_amax[TSTEPS * BATCH];
// bf16 2-way splits: value = sp0 + sp1
__device__ alignas(16) __nv_bfloat16 g_wsp[2][VOCAB * HIDDEN];
__device__ alignas(16) __nv_bfloat16 g_hsp[2][BATCH * HIDDEN];

// monotone float -> uint mapping for atomicMax-based argmax
__device__ __forceinline__ unsigned int ford(float f) {
    unsigned int u = __float_as_uint(f);
    return (u & 0x80000000u) ? ~u : (u | 0x80000000u);
}
__device__ __forceinline__ void split2(float v, __nv_bfloat16& a, __nv_bfloat16& b) {
    a = __float2bfloat16(v);
    b = __float2bfloat16(v - __bfloat162float(a));
}
__device__ __forceinline__ uint32_t smem_u32(const void* p) {
    uint32_t a;
    asm("{ .reg .u64 t; cvta.to.shared.u64 t, %1; cvt.u32.u64 %0, t; }"
        : "=r"(a) : "l"(p));
    return a;
}
__device__ __forceinline__ void ldsm4(uint32_t* r, uint32_t addr) {
    asm volatile("ldmatrix.sync.aligned.m8n8.x4.shared.b16 {%0,%1,%2,%3}, [%4];"
                 : "=r"(r[0]), "=r"(r[1]), "=r"(r[2]), "=r"(r[3]) : "r"(addr));
}
__device__ __forceinline__ void mma16816(float* d, const uint32_t* a, const uint32_t* b) {
    asm volatile(
        "mma.sync.aligned.m16n8k16.row.col.f32.bf16.bf16.f32 "
        "{%0,%1,%2,%3}, {%4,%5,%6,%7}, {%8,%9}, {%0,%1,%2,%3};"
        : "+f"(d[0]), "+f"(d[1]), "+f"(d[2]), "+f"(d[3])
        : "r"(a[0]), "r"(a[1]), "r"(a[2]), "r"(a[3]), "r"(b[0]), "r"(b[1]));
}

// ---------------- init ----------------
__global__ void init_kernel(const float* __restrict__ hidden,
                            const float* __restrict__ cell) {
    int i = blockIdx.x * blockDim.x + threadIdx.x;
    if (i < BATCH * HIDDEN) {
        g_h[0][i] = hidden[i];
        g_c[i]    = cell[i];
    }
    if (i < TSTEPS * BATCH) g_amax[i] = 0ull;
}

// ---------------- split fc_w into 2 bf16 components (once) ----------------
__global__ __launch_bounds__(256) void split_w_kernel(const float* __restrict__ fc_w) {
    int i0 = (blockIdx.x * 256 + threadIdx.x) * 4;
    if (i0 >= VOCAB * HIDDEN) return;
    float4 v = *(const float4*)(fc_w + i0);
    float vv[4] = {v.x, v.y, v.z, v.w};
    #pragma unroll
    for (int j = 0; j < 4; j++) {
        __nv_bfloat16 a, b;
        split2(vv[j], a, b);
        g_wsp[0][i0 + j] = a;
        g_wsp[1][i0 + j] = b;
    }
}

// ---------------- LSTM step: 1024 threads, 4-way k-split ----------------
// grid (64, 2): 64 unit-blocks of 8 units x 2 batch-halves of 32.
// thread: kh = tid>>8 (k quarter), m = tid&31 (batch in half), q = (tid>>5)&7 (unit)
__global__ __launch_bounds__(1024) void lstm_step_kernel(
    const float* __restrict__ embedding,
    const float* __restrict__ w_ih,
    const float* __restrict__ w_hh,
    const float* __restrict__ b_ih,
    const float* __restrict__ b_hh,
    const int*   __restrict__ start_tok,
    int t)
{
    __shared__ float  As[128][33];     // [k][b]  16896 B, conflict-free
    __shared__ float  Ws[128][36];     // [k][rp] 18432 B, rp = q*4+gate (32 used)
    __shared__ float4 pacc[3][256];    // 12288 B partial sums
    __shared__ int    toks[32];

    const int tid = threadIdx.x;
    const int bx  = blockIdx.x;     // unit block
    const int by  = blockIdx.y;     // batch half
    const int j0  = bx * 8;
    const int rb  = t & 1, wb = rb ^ 1;

    if (tid < 32) {
        if (t == 0) toks[tid] = *start_tok;
        else {
            unsigned long long key = g_amax[(t - 1) * BATCH + by * 32 + tid];
            toks[tid] = (int)(~((unsigned int)(key & 0xFFFFFFFFull)));
        }
    }
    __syncthreads();

    const int kh   = tid >> 8;      // 0..3
    const int htid = tid & 255;
    const int m    = htid & 31;
    const int q    = htid >> 5;     // 0..7

    // loader mapping: each of 1024 threads loads one float4 per matrix per chunk
    const int lb  = tid & 31;           // row (batch / gate-row)
    const int ks4 = (tid >> 5) * 4;     // k offset 0..124

    float acc0 = 0.f, acc1 = 0.f, acc2 = 0.f, acc3 = 0.f;

    for (int kc = 0; kc < 8; kc++) {
        const int kbase = kc * 128;
        {   // activations: A[b][k] -> As[k][b]
            const float* src = (kbase < EMBED)
                ? embedding + (size_t)toks[lb] * EMBED + kbase + ks4
                : g_h[rb] + (by * 32 + lb) * HIDDEN + (kbase - EMBED) + ks4;
            float4 v = *(const float4*)src;
            As[ks4    ][lb] = v.x; As[ks4 + 1][lb] = v.y;
            As[ks4 + 2][lb] = v.z; As[ks4 + 3][lb] = v.w;
        }
        {   // weights: row R = gate*512 + unit, gate = lb&3, unit = j0 + (lb>>2)
            const int R = (lb & 3) * HIDDEN + j0 + (lb >> 2);
            const float* src = (kbase < EMBED)
                ? w_ih + (size_t)R * EMBED + kbase + ks4
                : w_hh + (size_t)R * HIDDEN + (kbase - EMBED) + ks4;
            float4 v = *(const float4*)src;
            Ws[ks4    ][lb] = v.x; Ws[ks4 + 1][lb] = v.y;
            Ws[ks4 + 2][lb] = v.z; Ws[ks4 + 3][lb] = v.w;
        }
        __syncthreads();

        const int k0 = kh * 32;
        #pragma unroll
        for (int k = 0; k < 32; k++) {
            float  a = As[k0 + k][m];
            float4 w = *(const float4*)&Ws[k0 + k][q * 4];
            acc0 += a * w.x; acc1 += a * w.y; acc2 += a * w.z; acc3 += a * w.w;
        }
        __syncthreads();
    }

    if (kh > 0) pacc[kh - 1][htid] = make_float4(acc0, acc1, acc2, acc3);
    __syncthreads();

    if (kh == 0) {
        #pragma unroll
        for (int p = 0; p < 3; p++) {
            float4 v = pacc[p][htid];
            acc0 += v.x; acc1 += v.y; acc2 += v.z; acc3 += v.w;
        }
        const int unit = j0 + q;
        acc0 += b_ih[0 * HIDDEN + unit] + b_hh[0 * HIDDEN + unit];
        acc1 += b_ih[1 * HIDDEN + unit] + b_hh[1 * HIDDEN + unit];
        acc2 += b_ih[2 * HIDDEN + unit] + b_hh[2 * HIDDEN + unit];
        acc3 += b_ih[3 * HIDDEN + unit] + b_hh[3 * HIDDEN + unit];

        float ig = 1.f / (1.f + expf(-acc0));
        float fg = 1.f / (1.f + expf(-acc1));
        float gg = tanhf(acc2);
        float og = 1.f / (1.f + expf(-acc3));

        const int ci = (by * 32 + m) * HIDDEN + unit;
        float c = fg * g_c[ci] + ig * gg;
        g_c[ci] = c;
        float hv = og * tanhf(c);
        g_h[wb][ci] = hv;

        __nv_bfloat16 h0, h1;
        split2(hv, h0, h1);
        g_hsp[0][ci] = h0;
        g_hsp[1][ci] = h1;
    }
}

// ---------------- fc: HMMA bf16x2-split GEMM + bias + store + argmax ----------
// Per CTA (256 thr, 8 warps): D[128 vocab x 64 batch], warp w owns m rows w*16..+15.
// K in 8 chunks of 64.  smem: Wt[2][128][64bf16] @0 (32KB, SW128-style swizzle),
// Ht[2][64][64bf16] @32768 (16KB).  Epilogue reuses smem as Ds[64][132] f32.
#define FC_SMEM 49152

__global__ void __launch_bounds__(256, 2) fc_tc_kernel(
    const float* __restrict__ fc_b, float* __restrict__ out, int t)
{
    extern __shared__ char smem[];
    const int tid  = threadIdx.x;
    const int wid  = tid >> 5;
    const int lane = tid & 31;
    const int v0   = blockIdx.x * 128;
    const uint32_t sW = smem_u32(smem);
    const uint32_t sH = sW + 32768;

    float acc[8][4];
    #pragma unroll
    for (int i = 0; i < 8; i++)
        acc[i][0] = acc[i][1] = acc[i][2] = acc[i][3] = 0.f;

    for (int ck = 0; ck < 8; ck++) {
        // ---- W tiles: 2 splits x [128 rows x 64 bf16] (row = 8 x 16B chunks)
        #pragma unroll
        for (int s = 0; s < 2; s++) {
            const uint4* src = (const uint4*)(g_wsp[s] + (size_t)v0 * HIDDEN + ck * 64);
            #pragma unroll
            for (int i = 0; i < 4; i++) {
                int idx = tid + i * 256;
                int r = idx >> 3, u = idx & 7;
                uint4 val = src[(size_t)r * 64 + u];
                *(uint4*)(smem + s * 16384 + r * 128 + ((u ^ (r & 7)) << 4)) = val;
            }
        }
        // ---- H tiles: 2 splits x [64 rows x 64 bf16]
        #pragma unroll
        for (int s = 0; s < 2; s++) {
            const uint4* src = (const uint4*)(g_hsp[s] + ck * 64);
            #pragma unroll
            for (int i = 0; i < 2; i++) {
                int idx = tid + i * 256;
                int r = idx >> 3, u = idx & 7;
                uint4 val = src[(size_t)r * 64 + u];
                *(uint4*)(smem + 32768 + s * 8192 + r * 128 + ((u ^ (r & 7)) << 4)) = val;
            }
        }
        __syncthreads();

        #pragma unroll
        for (int ks = 0; ks < 4; ks++) {
            // A fragments (m16k16) for both W splits
            uint32_t a0[4], a1[4];
            {
                int row = wid * 16 + (lane & 15);
                int u   = (ks << 1) + (lane >> 4);
                uint32_t addr = sW + row * 128 + ((u ^ (row & 7)) << 4);
                ldsm4(a0, addr);
                ldsm4(a1, addr + 16384);
            }
            // B fragments: 8 n-tiles (n8k16) per split, 4 x4-loads each
            uint32_t b0[16], b1[16];
            #pragma unroll
            for (int g = 0; g < 4; g++) {
                int n = g * 16 + ((lane >> 4) << 3) + (lane & 7);
                int u = (ks << 1) + ((lane >> 3) & 1);
                uint32_t addr = sH + n * 128 + ((u ^ (n & 7)) << 4);
                ldsm4(&b0[g * 4], addr);
                ldsm4(&b1[g * 4], addr + 8192);
            }
            // combos: hi*hi + hi*lo + lo*hi
            #pragma unroll
            for (int nt = 0; nt < 8; nt++) {
                mma16816(acc[nt], a0, &b0[nt * 2]);
                mma16816(acc[nt], a0, &b1[nt * 2]);
                mma16816(acc[nt], a1, &b0[nt * 2]);
            }
        }
        __syncthreads();
    }

    // ---- stage D to smem transposed: Ds[b][m], pitch 132 (conflict-free)
    float* Ds = (float*)smem;
    #pragma unroll
    for (int nt = 0; nt < 8; nt++) {
        int bb = nt * 8 + ((lane & 3) << 1);
        int mm = wid * 16 + (lane >> 2);
        float* p = Ds + bb * 132 + mm;
        p[0]   = acc[nt][0];   // (b,   m)
        p[132] = acc[nt][1];   // (b+1, m)
        p[8]   = acc[nt][2];   // (b,   m+8)
        p[140] = acc[nt][3];   // (b+1, m+8)
    }
    __syncthreads();

    // ---- bias + coalesced store + fused argmax (thread owns one batch b)
    const int b  = tid >> 2;
    const int cg = tid & 3;
    float* orow = out + (size_t)b * (TSTEPS * VOCAB) + (size_t)t * VOCAB + v0;
    float bestv = -3.4e38f;
    int   bestn = 0;
    #pragma unroll
    for (int i = 0; i < 8; i++) {
        int mm = cg * 4 + i * 16;
        float4 v  = *(const float4*)(Ds + b * 132 + mm);
        float4 bi = *(const float4*)(fc_b + v0 + mm);
        float r0 = v.x + bi.x, r1 = v.y + bi.y, r2 = v.z + bi.z, r3 = v.w + bi.w;
        *(float4*)(orow + mm) = make_float4(r0, r1, r2, r3);
        if (r0 > bestv) { bestv = r0; bestn = v0 + mm;     }
        if (r1 > bestv) { bestv = r1; bestn = v0 + mm + 1; }
        if (r2 > bestv) { bestv = r2; bestn = v0 + mm + 2; }
        if (r3 > bestv) { bestv = r3; bestn = v0 + mm + 3; }
    }
    unsigned long long key =
        ((unsigned long long)ford(bestv) << 32) | (unsigned)(~bestn);
    #pragma unroll
    for (int off = 1; off < 4; off <<= 1) {
        unsigned long long ok = __shfl_xor_sync(0xffffffffu, key, off);
        if (ok > key) key = ok;
    }
    if (cg == 0) atomicMax(&g_amax[t * BATCH + b], key);
}

// ---------------- launch ----------------
extern "C" void kernel_launch(void* const* d_in, const int* in_sizes, int n_in,
                              void* d_out, int out_size) {
    const float* hidden    = (const float*)d_in[0];
    const float* cell      = (const float*)d_in[1];
    /* d_in[2] = max_length (compile-time TSTEPS) */
    const int*   start_tok = (const int*)d_in[3];
    const float* embedding = (const float*)d_in[4];
    const float* w_ih      = (const float*)d_in[5];
    const float* w_hh      = (const float*)d_in[6];
    const float* b_ih      = (const float*)d_in[7];
    const float* b_hh      = (const float*)d_in[8];
    const float* fc_w      = (const float*)d_in[9];
    const float* fc_b      = (const float*)d_in[10];
    float* out = (float*)d_out;

    init_kernel<<<128, 256>>>(hidden, cell);
    split_w_kernel<<<VOCAB * HIDDEN / (256 * 4), 256>>>(fc_w);
    for (int t = 0; t < TSTEPS; t++) {
        lstm_step_kernel<<<dim3(64, 2), 1024>>>(embedding, w_ih, w_hh,
                                                b_ih, b_hh, start_tok, t);
        fc_tc_kernel<<<VOCAB / 128, 256, FC_SMEM>>>(fc_b, out, t);
    }
}

// round 9
// speedup vs baseline: 2.9450x; 1.7263x over previous
#include <cuda_runtime.h>
#include <cuda_bf16.h>
#include <cstdint>

#define VOCAB  32000
#define EMBED  512
#define HIDDEN 512
#define BATCH  64
#define TSTEPS 64

// -------- persistent scratch (no allocs allowed) --------
__device__ float g_h[2][BATCH * HIDDEN];
__device__ float g_c[BATCH * HIDDEN];
__device__ unsigned long long g_amax[TSTEPS * BATCH];
// bf16 2-way splits: value = sp0 + sp1
__device__ alignas(16) __nv_bfloat16 g_wsp[2][VOCAB * HIDDEN];
__device__ alignas(16) __nv_bfloat16 g_hsp[2][BATCH * HIDDEN];

// monotone float -> uint mapping for atomicMax-based argmax
__device__ __forceinline__ unsigned int ford(float f) {
    unsigned int u = __float_as_uint(f);
    return (u & 0x80000000u) ? ~u : (u | 0x80000000u);
}
__device__ __forceinline__ void split2(float v, __nv_bfloat16& a, __nv_bfloat16& b) {
    a = __float2bfloat16(v);
    b = __float2bfloat16(v - __bfloat162float(a));
}
__device__ __forceinline__ uint32_t smem_u32(const void* p) {
    uint32_t a;
    asm("{ .reg .u64 t; cvta.to.shared.u64 t, %1; cvt.u32.u64 %0, t; }"
        : "=r"(a) : "l"(p));
    return a;
}
__device__ __forceinline__ void ldsm4(uint32_t* r, uint32_t addr) {
    asm volatile("ldmatrix.sync.aligned.m8n8.x4.shared.b16 {%0,%1,%2,%3}, [%4];"
                 : "=r"(r[0]), "=r"(r[1]), "=r"(r[2]), "=r"(r[3]) : "r"(addr));
}
__device__ __forceinline__ void mma16816(float* d, const uint32_t* a, const uint32_t* b) {
    asm volatile(
        "mma.sync.aligned.m16n8k16.row.col.f32.bf16.bf16.f32 "
        "{%0,%1,%2,%3}, {%4,%5,%6,%7}, {%8,%9}, {%0,%1,%2,%3};"
        : "+f"(d[0]), "+f"(d[1]), "+f"(d[2]), "+f"(d[3])
        : "r"(a[0]), "r"(a[1]), "r"(a[2]), "r"(a[3]), "r"(b[0]), "r"(b[1]));
}
__device__ __forceinline__ void cpasync16(uint32_t dst, const void* src) {
    asm volatile("cp.async.cg.shared.global [%0], [%1], 16;"
                 :: "r"(dst), "l"((const void*)__cvta_generic_to_global(src))
                 : "memory");
}
__device__ __forceinline__ void cp_commit() {
    asm volatile("cp.async.commit_group;" ::: "memory");
}

// ---------------- init ----------------
__global__ void init_kernel(const float* __restrict__ hidden,
                            const float* __restrict__ cell) {
    int i = blockIdx.x * blockDim.x + threadIdx.x;
    if (i < BATCH * HIDDEN) {
        g_h[0][i] = hidden[i];
        g_c[i]    = cell[i];
    }
    if (i < TSTEPS * BATCH) g_amax[i] = 0ull;
}

// ---------------- split fc_w into 2 bf16 components (once) ----------------
__global__ __launch_bounds__(256) void split_w_kernel(const float* __restrict__ fc_w) {
    int i0 = (blockIdx.x * 256 + threadIdx.x) * 4;
    if (i0 >= VOCAB * HIDDEN) return;
    float4 v = *(const float4*)(fc_w + i0);
    float vv[4] = {v.x, v.y, v.z, v.w};
    #pragma unroll
    for (int j = 0; j < 4; j++) {
        __nv_bfloat16 a, b;
        split2(vv[j], a, b);
        g_wsp[0][i0 + j] = a;
        g_wsp[1][i0 + j] = b;
    }
}

// ---------------- LSTM step: 1024 thr, 4-way k-split, double-buffered ------
// grid (64, 2). dynamic smem layout (bytes):
//   As [2][128][33] f32 @0       (33792)
//   Ws [2][128][36] f32 @33792   (36864)
//   pacc [3][256] float4 @70656  (12288)
//   toks [32] int @82944
#define LSTM_SMEM 83072

__global__ __launch_bounds__(1024) void lstm_step_kernel(
    const float* __restrict__ embedding,
    const float* __restrict__ w_ih,
    const float* __restrict__ w_hh,
    const float* __restrict__ b_ih,
    const float* __restrict__ b_hh,
    const int*   __restrict__ start_tok,
    int t)
{
    extern __shared__ char lsm[];
    float*  As   = (float*)lsm;               // [2][128][33]
    float*  Ws   = (float*)(lsm + 33792);     // [2][128][36]
    float4* pacc = (float4*)(lsm + 70656);    // [3][256]
    int*    toks = (int*)(lsm + 82944);

    const int tid = threadIdx.x;
    const int bx  = blockIdx.x;
    const int by  = blockIdx.y;
    const int j0  = bx * 8;
    const int rb  = t & 1, wb = rb ^ 1;

    if (tid < 32) {
        if (t == 0) toks[tid] = *start_tok;
        else {
            unsigned long long key = g_amax[(t - 1) * BATCH + by * 32 + tid];
            toks[tid] = (int)(~((unsigned int)(key & 0xFFFFFFFFull)));
        }
    }
    __syncthreads();

    const int kh   = tid >> 8;
    const int htid = tid & 255;
    const int m    = htid & 31;
    const int q    = htid >> 5;

    const int lb  = tid & 31;
    const int ks4 = (tid >> 5) * 4;
    const int R   = (lb & 3) * HIDDEN + j0 + (lb >> 2);

    // ---- chunk loaders (one float4 per matrix per thread)
    auto ldgA = [&](int kc) -> float4 {
        const int kbase = kc * 128;
        const float* src = (kbase < EMBED)
            ? embedding + (size_t)toks[lb] * EMBED + kbase + ks4
            : g_h[rb] + (by * 32 + lb) * HIDDEN + (kbase - EMBED) + ks4;
        return *(const float4*)src;
    };
    auto ldgW = [&](int kc) -> float4 {
        const int kbase = kc * 128;
        const float* src = (kbase < EMBED)
            ? w_ih + (size_t)R * EMBED + kbase + ks4
            : w_hh + (size_t)R * HIDDEN + (kbase - EMBED) + ks4;
        return *(const float4*)src;
    };
    auto stsAW = [&](int buf, float4 va, float4 vw) {
        float* ap = As + (size_t)(buf * 128 + ks4) * 33 + lb;
        ap[0] = va.x; ap[33] = va.y; ap[66] = va.z; ap[99] = va.w;
        float* wp = Ws + (size_t)(buf * 128 + ks4) * 36 + lb;
        wp[0] = vw.x; wp[36] = vw.y; wp[72] = vw.z; wp[108] = vw.w;
    };

    float acc0 = 0.f, acc1 = 0.f, acc2 = 0.f, acc3 = 0.f;

    {   // prologue: fill buf 0
        float4 va = ldgA(0), vw = ldgW(0);
        stsAW(0, va, vw);
    }
    __syncthreads();

    for (int kc = 0; kc < 8; kc++) {
        const int buf = kc & 1;
        float4 va, vw;
        if (kc < 7) { va = ldgA(kc + 1); vw = ldgW(kc + 1); }

        const int k0 = buf * 128 + kh * 32;
        #pragma unroll
        for (int k = 0; k < 32; k++) {
            float  a = As[(size_t)(k0 + k) * 33 + m];
            float4 w = *(const float4*)&Ws[(size_t)(k0 + k) * 36 + q * 4];
            acc0 += a * w.x; acc1 += a * w.y; acc2 += a * w.z; acc3 += a * w.w;
        }

        if (kc < 7) stsAW(buf ^ 1, va, vw);
        __syncthreads();
    }

    if (kh > 0) pacc[(kh - 1) * 256 + htid] = make_float4(acc0, acc1, acc2, acc3);
    __syncthreads();

    if (kh == 0) {
        #pragma unroll
        for (int p = 0; p < 3; p++) {
            float4 v = pacc[p * 256 + htid];
            acc0 += v.x; acc1 += v.y; acc2 += v.z; acc3 += v.w;
        }
        const int unit = j0 + q;
        acc0 += b_ih[0 * HIDDEN + unit] + b_hh[0 * HIDDEN + unit];
        acc1 += b_ih[1 * HIDDEN + unit] + b_hh[1 * HIDDEN + unit];
        acc2 += b_ih[2 * HIDDEN + unit] + b_hh[2 * HIDDEN + unit];
        acc3 += b_ih[3 * HIDDEN + unit] + b_hh[3 * HIDDEN + unit];

        float ig = 1.f / (1.f + expf(-acc0));
        float fg = 1.f / (1.f + expf(-acc1));
        float gg = tanhf(acc2);
        float og = 1.f / (1.f + expf(-acc3));

        const int ci = (by * 32 + m) * HIDDEN + unit;
        float c = fg * g_c[ci] + ig * gg;
        g_c[ci] = c;
        float hv = og * tanhf(c);
        g_h[wb][ci] = hv;

        __nv_bfloat16 h0, h1;
        split2(hv, h0, h1);
        g_hsp[0][ci] = h0;
        g_hsp[1][ci] = h1;
    }
}

// ---------------- fc: HMMA bf16x2-split GEMM, cp.async double-buffered ------
// 256 thr / 8 warps, tile [128v x 64b], K in 8 chunks of 64.
// stage layout (48KB): W 2 x [128 x 128B] @0, H 2 x [64 x 128B] @32768.
// two stages -> 96KB dynamic; epilogue reuses stage 0 as Ds[64][132] f32.
#define FC_STAGE 49152
#define FC_SMEM  98304

__global__ void __launch_bounds__(256, 2) fc_tc_kernel(
    const float* __restrict__ fc_b, float* __restrict__ out, int t)
{
    extern __shared__ char smem[];
    const int tid  = threadIdx.x;
    const int wid  = tid >> 5;
    const int lane = tid & 31;
    const int v0   = blockIdx.x * 128;
    const uint32_t sbase = smem_u32(smem);

    auto load_chunk = [&](int ck, int buf) {
        const uint32_t sb = sbase + buf * FC_STAGE;
        #pragma unroll
        for (int s = 0; s < 2; s++) {
            const char* srcb = (const char*)(g_wsp[s] + (size_t)v0 * HIDDEN + ck * 64);
            #pragma unroll
            for (int i = 0; i < 4; i++) {
                int idx = tid + i * 256;
                int r = idx >> 3, u = idx & 7;
                cpasync16(sb + s * 16384 + r * 128 + ((u ^ (r & 7)) << 4),
                          srcb + (size_t)r * 1024 + u * 16);
            }
        }
        #pragma unroll
        for (int s = 0; s < 2; s++) {
            const char* srcb = (const char*)(g_hsp[s] + ck * 64);
            #pragma unroll
            for (int i = 0; i < 2; i++) {
                int idx = tid + i * 256;
                int r = idx >> 3, u = idx & 7;
                cpasync16(sb + 32768 + s * 8192 + r * 128 + ((u ^ (r & 7)) << 4),
                          srcb + (size_t)r * 1024 + u * 16);
            }
        }
        cp_commit();
    };

    float acc[8][4];
    #pragma unroll
    for (int i = 0; i < 8; i++)
        acc[i][0] = acc[i][1] = acc[i][2] = acc[i][3] = 0.f;

    load_chunk(0, 0);

    for (int ck = 0; ck < 8; ck++) {
        if (ck < 7) load_chunk(ck + 1, (ck + 1) & 1);
        if (ck < 7) asm volatile("cp.async.wait_group 1;" ::: "memory");
        else        asm volatile("cp.async.wait_group 0;" ::: "memory");
        __syncthreads();

        const uint32_t sW = sbase + (ck & 1) * FC_STAGE;
        const uint32_t sH = sW + 32768;

        #pragma unroll
        for (int ks = 0; ks < 4; ks++) {
            uint32_t a0[4], a1[4];
            {
                int row = wid * 16 + (lane & 15);
                int u   = (ks << 1) + (lane >> 4);
                uint32_t addr = sW + row * 128 + ((u ^ (row & 7)) << 4);
                ldsm4(a0, addr);
                ldsm4(a1, addr + 16384);
            }
            uint32_t b0[16], b1[16];
            #pragma unroll
            for (int g = 0; g < 4; g++) {
                int n = g * 16 + ((lane >> 4) << 3) + (lane & 7);
                int u = (ks << 1) + ((lane >> 3) & 1);
                uint32_t addr = sH + n * 128 + ((u ^ (n & 7)) << 4);
                ldsm4(&b0[g * 4], addr);
                ldsm4(&b1[g * 4], addr + 8192);
            }
            #pragma unroll
            for (int nt = 0; nt < 8; nt++) {
                mma16816(acc[nt], a0, &b0[nt * 2]);
                mma16816(acc[nt], a0, &b1[nt * 2]);
                mma16816(acc[nt], a1, &b0[nt * 2]);
            }
        }
        __syncthreads();
    }

    // ---- stage D to smem transposed: Ds[b][m], pitch 132 (stage-0 region)
    float* Ds = (float*)smem;
    #pragma unroll
    for (int nt = 0; nt < 8; nt++) {
        int bb = nt * 8 + ((lane & 3) << 1);
        int mm = wid * 16 + (lane >> 2);
        float* p = Ds + bb * 132 + mm;
        p[0]   = acc[nt][0];
        p[132] = acc[nt][1];
        p[8]   = acc[nt][2];
        p[140] = acc[nt][3];
    }
    __syncthreads();

    // ---- bias + coalesced store + fused argmax (thread owns one batch b)
    const int b  = tid >> 2;
    const int cg = tid & 3;
    float* orow = out + (size_t)b * (TSTEPS * VOCAB) + (size_t)t * VOCAB + v0;
    float bestv = -3.4e38f;
    int   bestn = 0;
    #pragma unroll
    for (int i = 0; i < 8; i++) {
        int mm = cg * 4 + i * 16;
        float4 v  = *(const float4*)(Ds + b * 132 + mm);
        float4 bi = *(const float4*)(fc_b + v0 + mm);
        float r0 = v.x + bi.x, r1 = v.y + bi.y, r2 = v.z + bi.z, r3 = v.w + bi.w;
        *(float4*)(orow + mm) = make_float4(r0, r1, r2, r3);
        if (r0 > bestv) { bestv = r0; bestn = v0 + mm;     }
        if (r1 > bestv) { bestv = r1; bestn = v0 + mm + 1; }
        if (r2 > bestv) { bestv = r2; bestn = v0 + mm + 2; }
        if (r3 > bestv) { bestv = r3; bestn = v0 + mm + 3; }
    }
    unsigned long long key =
        ((unsigned long long)ford(bestv) << 32) | (unsigned)(~bestn);
    #pragma unroll
    for (int off = 1; off < 4; off <<= 1) {
        unsigned long long ok = __shfl_xor_sync(0xffffffffu, key, off);
        if (ok > key) key = ok;
    }
    if (cg == 0) atomicMax(&g_amax[t * BATCH + b], key);
}

// ---------------- launch ----------------
extern "C" void kernel_launch(void* const* d_in, const int* in_sizes, int n_in,
                              void* d_out, int out_size) {
    const float* hidden    = (const float*)d_in[0];
    const float* cell      = (const float*)d_in[1];
    /* d_in[2] = max_length (compile-time TSTEPS) */
    const int*   start_tok = (const int*)d_in[3];
    const float* embedding = (const float*)d_in[4];
    const float* w_ih      = (const float*)d_in[5];
    const float* w_hh      = (const float*)d_in[6];
    const float* b_ih      = (const float*)d_in[7];
    const float* b_hh      = (const float*)d_in[8];
    const float* fc_w      = (const float*)d_in[9];
    const float* fc_b      = (const float*)d_in[10];
    float* out = (float*)d_out;

    cudaFuncSetAttribute(fc_tc_kernel,
                         cudaFuncAttributeMaxDynamicSharedMemorySize, FC_SMEM);
    cudaFuncSetAttribute(lstm_step_kernel,
                         cudaFuncAttributeMaxDynamicSharedMemorySize, LSTM_SMEM);

    init_kernel<<<128, 256>>>(hidden, cell);
    split_w_kernel<<<VOCAB * HIDDEN / (256 * 4), 256>>>(fc_w);
    for (int t = 0; t < TSTEPS; t++) {
        lstm_step_kernel<<<dim3(64, 2), 1024, LSTM_SMEM>>>(
            embedding, w_ih, w_hh, b_ih, b_hh, start_tok, t);
        fc_tc_kernel<<<VOCAB / 128, 256, FC_SMEM>>>(fc_b, out, t);
    }
}

// round 13
// speedup vs baseline: 2.9512x; 1.0021x over previous
#include <cuda_runtime.h>
#include <cuda_bf16.h>
#include <cstdint>

#define VOCAB  32000
#define EMBED  512
#define HIDDEN 512
#define BATCH  64
#define TSTEPS 64

// -------- persistent scratch (no allocs allowed) --------
__device__ float g_h[2][BATCH * HIDDEN];
__device__ float g_c[BATCH * HIDDEN];
__device__ unsigned long long g_amax[TSTEPS * BATCH];
// bf16 2-way splits: value = sp0 + sp1
__device__ alignas(16) __nv_bfloat16 g_wsp[2][VOCAB * HIDDEN];
__device__ alignas(16) __nv_bfloat16 g_hsp[2][BATCH * HIDDEN];

// monotone float -> uint mapping for atomicMax-based argmax
__device__ __forceinline__ unsigned int ford(float f) {
    unsigned int u = __float_as_uint(f);
    return (u & 0x80000000u) ? ~u : (u | 0x80000000u);
}
__device__ __forceinline__ void split2(float v, __nv_bfloat16& a, __nv_bfloat16& b) {
    a = __float2bfloat16(v);
    b = __float2bfloat16(v - __bfloat162float(a));
}
__device__ __forceinline__ uint32_t smem_u32(const void* p) {
    uint32_t a;
    asm("{ .reg .u64 t; cvta.to.shared.u64 t, %1; cvt.u32.u64 %0, t; }"
        : "=r"(a) : "l"(p));
    return a;
}
__device__ __forceinline__ void ldsm4(uint32_t* r, uint32_t addr) {
    asm volatile("ldmatrix.sync.aligned.m8n8.x4.shared.b16 {%0,%1,%2,%3}, [%4];"
                 : "=r"(r[0]), "=r"(r[1]), "=r"(r[2]), "=r"(r[3]) : "r"(addr));
}
__device__ __forceinline__ void mma16816(float* d, const uint32_t* a, const uint32_t* b) {
    asm volatile(
        "mma.sync.aligned.m16n8k16.row.col.f32.bf16.bf16.f32 "
        "{%0,%1,%2,%3}, {%4,%5,%6,%7}, {%8,%9}, {%0,%1,%2,%3};"
        : "+f"(d[0]), "+f"(d[1]), "+f"(d[2]), "+f"(d[3])
        : "r"(a[0]), "r"(a[1]), "r"(a[2]), "r"(a[3]), "r"(b[0]), "r"(b[1]));
}
__device__ __forceinline__ void cpasync16(uint32_t dst, const void* src) {
    asm volatile("cp.async.cg.shared.global [%0], [%1], 16;"
                 :: "r"(dst), "l"((const void*)__cvta_generic_to_global(src))
                 : "memory");
}
__device__ __forceinline__ void cp_commit() {
    asm volatile("cp.async.commit_group;" ::: "memory");
}

// ---------------- init ----------------
__global__ void init_kernel(const float* __restrict__ hidden,
                            const float* __restrict__ cell) {
    int i = blockIdx.x * blockDim.x + threadIdx.x;
    if (i < BATCH * HIDDEN) {
        g_h[0][i] = hidden[i];
        g_c[i]    = cell[i];
    }
    if (i < TSTEPS * BATCH) g_amax[i] = 0ull;
}

// ---------------- split fc_w into 2 bf16 components (once) ----------------
__global__ __launch_bounds__(256) void split_w_kernel(const float* __restrict__ fc_w) {
    int i0 = (blockIdx.x * 256 + threadIdx.x) * 4;
    if (i0 >= VOCAB * HIDDEN) return;
    float4 v = *(const float4*)(fc_w + i0);
    float vv[4] = {v.x, v.y, v.z, v.w};
    #pragma unroll
    for (int j = 0; j < 4; j++) {
        __nv_bfloat16 a, b;
        split2(vv[j], a, b);
        g_wsp[0][i0 + j] = a;
        g_wsp[1][i0 + j] = b;
    }
}

// ---------------- LSTM step: 1024 thr, 4-way k-split, double-buffered ------
// grid (64, 2). dynamic smem layout (bytes):
//   As [2][128][33] f32 @0       (33792)
//   Ws [2][128][36] f32 @33792   (36864)
//   pacc [3][256] float4 @70656  (12288)
//   toks [32] int @82944
//   sc [32][8] f32 @83072 (old c in, new c out)
//   sh [32][8] f32 @84096
#define LSTM_SMEM 85120

__global__ __launch_bounds__(1024) void lstm_step_kernel(
    const float* __restrict__ embedding,
    const float* __restrict__ w_ih,
    const float* __restrict__ w_hh,
    const float* __restrict__ b_ih,
    const float* __restrict__ b_hh,
    const int*   __restrict__ start_tok,
    int t)
{
    extern __shared__ char lsm[];
    float*  As   = (float*)lsm;               // [2][128][33]
    float*  Ws   = (float*)(lsm + 33792);     // [2][128][36]
    float4* pacc = (float4*)(lsm + 70656);    // [3][256]
    int*    toks = (int*)(lsm + 82944);
    float*  sc   = (float*)(lsm + 83072);     // [32][8]
    float*  sh   = (float*)(lsm + 84096);     // [32][8]

    const int tid = threadIdx.x;
    const int bx  = blockIdx.x;
    const int by  = blockIdx.y;
    const int j0  = bx * 8;
    const int rb  = t & 1, wb = rb ^ 1;

    if (tid < 32) {
        if (t == 0) toks[tid] = *start_tok;
        else {
            unsigned long long key = g_amax[(t - 1) * BATCH + by * 32 + tid];
            toks[tid] = (int)(~((unsigned int)(key & 0xFFFFFFFFull)));
        }
    }
    if (tid < 256) {   // coalesced old-c preload: 8 lanes -> 32B contiguous
        int b = tid >> 3, u = tid & 7;
        sc[tid] = g_c[(by * 32 + b) * HIDDEN + j0 + u];
    }
    __syncthreads();

    const int kh   = tid >> 8;
    const int htid = tid & 255;
    const int m    = htid & 31;
    const int q    = htid >> 5;

    const int lb  = tid & 31;
    const int ks4 = (tid >> 5) * 4;
    const int R   = (lb & 3) * HIDDEN + j0 + (lb >> 2);

    auto ldgA = [&](int kc) -> float4 {
        const int kbase = kc * 128;
        const float* src = (kbase < EMBED)
            ? embedding + (size_t)toks[lb] * EMBED + kbase + ks4
            : g_h[rb] + (by * 32 + lb) * HIDDEN + (kbase - EMBED) + ks4;
        return *(const float4*)src;
    };
    auto ldgW = [&](int kc) -> float4 {
        const int kbase = kc * 128;
        const float* src = (kbase < EMBED)
            ? w_ih + (size_t)R * EMBED + kbase + ks4
            : w_hh + (size_t)R * HIDDEN + (kbase - EMBED) + ks4;
        return *(const float4*)src;
    };
    auto stsAW = [&](int buf, float4 va, float4 vw) {
        float* ap = As + (size_t)(buf * 128 + ks4) * 33 + lb;
        ap[0] = va.x; ap[33] = va.y; ap[66] = va.z; ap[99] = va.w;
        float* wp = Ws + (size_t)(buf * 128 + ks4) * 36 + lb;
        wp[0] = vw.x; wp[36] = vw.y; wp[72] = vw.z; wp[108] = vw.w;
    };

    float acc0 = 0.f, acc1 = 0.f, acc2 = 0.f, acc3 = 0.f;

    {
        float4 va = ldgA(0), vw = ldgW(0);
        stsAW(0, va, vw);
    }
    __syncthreads();

    for (int kc = 0; kc < 8; kc++) {
        const int buf = kc & 1;
        float4 va, vw;
        if (kc < 7) { va = ldgA(kc + 1); vw = ldgW(kc + 1); }

        const int k0 = buf * 128 + kh * 32;
        #pragma unroll
        for (int k = 0; k < 32; k++) {
            float  a = As[(size_t)(k0 + k) * 33 + m];
            float4 w = *(const float4*)&Ws[(size_t)(k0 + k) * 36 + q * 4];
            acc0 += a * w.x; acc1 += a * w.y; acc2 += a * w.z; acc3 += a * w.w;
        }

        if (kc < 7) stsAW(buf ^ 1, va, vw);
        __syncthreads();
    }

    if (kh > 0) pacc[(kh - 1) * 256 + htid] = make_float4(acc0, acc1, acc2, acc3);
    __syncthreads();

    if (kh == 0) {
        #pragma unroll
        for (int p = 0; p < 3; p++) {
            float4 v = pacc[p * 256 + htid];
            acc0 += v.x; acc1 += v.y; acc2 += v.z; acc3 += v.w;
        }
        const int unit = j0 + q;
        acc0 += b_ih[0 * HIDDEN + unit] + b_hh[0 * HIDDEN + unit];
        acc1 += b_ih[1 * HIDDEN + unit] + b_hh[1 * HIDDEN + unit];
        acc2 += b_ih[2 * HIDDEN + unit] + b_hh[2 * HIDDEN + unit];
        acc3 += b_ih[3 * HIDDEN + unit] + b_hh[3 * HIDDEN + unit];

        float ig = 1.f / (1.f + expf(-acc0));
        float fg = 1.f / (1.f + expf(-acc1));
        float gg = tanhf(acc2);
        float og = 1.f / (1.f + expf(-acc3));

        const int slot = m * 8 + q;
        float c = fg * sc[slot] + ig * gg;     // sc holds old c
        float hv = og * tanhf(c);
        sc[slot] = c;                          // stage new c
        sh[slot] = hv;
    }
    __syncthreads();

    if (tid < 256) {   // coalesced writeback: c, h, hsp0, hsp1
        int b = tid >> 3, u = tid & 7;
        const int ci = (by * 32 + b) * HIDDEN + j0 + u;
        float c  = sc[tid];
        float hv = sh[tid];
        g_c[ci] = c;
        g_h[wb][ci] = hv;
        __nv_bfloat16 h0, h1;
        split2(hv, h0, h1);
        g_hsp[0][ci] = h0;
        g_hsp[1][ci] = h1;
    }
}

// ---------------- fc: HMMA bf16x2-split GEMM, Mtile=256, 4x2 warps ----------
// 256 thr / 8 warps, tile [256v x 64b], K in 8 chunks of 64, grid 125 (1/SM).
// stage (80KB): W 2 x [256 x 128B] @0, H 2 x [64 x 128B] @65536.
// two stages = 160KB dynamic; epilogue reuses smem as Ds[64][260] f32.
#define FC_STAGE 81920
#define FC_SMEM  163840

__global__ void __launch_bounds__(256, 1) fc_tc_kernel(
    const float* __restrict__ fc_b, float* __restrict__ out, int t)
{
    extern __shared__ char smem[];
    const int tid  = threadIdx.x;
    const int wid  = tid >> 5;
    const int lane = tid & 31;
    const int wm   = wid & 3;          // m block (64 rows)
    const int wn   = wid >> 2;         // n block (32 batches)
    const int v0   = blockIdx.x * 256;
    const uint32_t sbase = smem_u32(smem);

    auto load_chunk = [&](int ck, int buf) {
        const uint32_t sb = sbase + buf * FC_STAGE;
        #pragma unroll
        for (int s = 0; s < 2; s++) {
            const char* srcb = (const char*)(g_wsp[s] + (size_t)v0 * HIDDEN + ck * 64);
            #pragma unroll
            for (int i = 0; i < 8; i++) {
                int idx = tid + i * 256;           // 0..2047
                int r = idx >> 3, u = idx & 7;     // r 0..255
                cpasync16(sb + s * 32768 + r * 128 + ((u ^ (r & 7)) << 4),
                          srcb + (size_t)r * 1024 + u * 16);
            }
        }
        #pragma unroll
        for (int s = 0; s < 2; s++) {
            const char* srcb = (const char*)(g_hsp[s] + ck * 64);
            #pragma unroll
            for (int i = 0; i < 2; i++) {
                int idx = tid + i * 256;
                int r = idx >> 3, u = idx & 7;
                cpasync16(sb + 65536 + s * 8192 + r * 128 + ((u ^ (r & 7)) << 4),
                          srcb + (size_t)r * 1024 + u * 16);
            }
        }
        cp_commit();
    };

    float acc[16][4];   // [mt*4 + nt][frag]
    #pragma unroll
    for (int i = 0; i < 16; i++)
        acc[i][0] = acc[i][1] = acc[i][2] = acc[i][3] = 0.f;

    load_chunk(0, 0);

    for (int ck = 0; ck < 8; ck++) {
        if (ck < 7) load_chunk(ck + 1, (ck + 1) & 1);
        if (ck < 7) asm volatile("cp.async.wait_group 1;" ::: "memory");
        else        asm volatile("cp.async.wait_group 0;" ::: "memory");
        __syncthreads();

        const uint32_t sW = sbase + (ck & 1) * FC_STAGE;
        const uint32_t sH = sW + 65536;

        #pragma unroll
        for (int ks = 0; ks < 4; ks++) {
            uint32_t a0[16], a1[16];
            #pragma unroll
            for (int mt = 0; mt < 4; mt++) {
                int row = wm * 64 + mt * 16 + (lane & 15);
                int u   = (ks << 1) + (lane >> 4);
                uint32_t addr = sW + row * 128 + ((u ^ (row & 7)) << 4);
                ldsm4(&a0[mt * 4], addr);
                ldsm4(&a1[mt * 4], addr + 32768);
            }
            uint32_t b0[8], b1[8];
            #pragma unroll
            for (int g = 0; g < 2; g++) {
                int n = wn * 32 + g * 16 + ((lane >> 4) << 3) + (lane & 7);
                int u = (ks << 1) + ((lane >> 3) & 1);
                uint32_t addr = sH + n * 128 + ((u ^ (n & 7)) << 4);
                ldsm4(&b0[g * 4], addr);
                ldsm4(&b1[g * 4], addr + 8192);
            }
            #pragma unroll
            for (int mt = 0; mt < 4; mt++)
                #pragma unroll
                for (int nt = 0; nt < 4; nt++) {
                    mma16816(acc[mt * 4 + nt], &a0[mt * 4], &b0[nt * 2]);
                    mma16816(acc[mt * 4 + nt], &a0[mt * 4], &b1[nt * 2]);
                    mma16816(acc[mt * 4 + nt], &a1[mt * 4], &b0[nt * 2]);
                }
        }
        __syncthreads();
    }

    // ---- stage D to smem transposed: Ds[b][m], pitch 260
    float* Ds = (float*)smem;
    #pragma unroll
    for (int mt = 0; mt < 4; mt++)
        #pragma unroll
        for (int nt = 0; nt < 4; nt++) {
            int bb = wn * 32 + nt * 8 + ((lane & 3) << 1);
            int mm = wm * 64 + mt * 16 + (lane >> 2);
            float* p = Ds + bb * 260 + mm;
            p[0]   = acc[mt * 4 + nt][0];
            p[260] = acc[mt * 4 + nt][1];
            p[8]   = acc[mt * 4 + nt][2];
            p[268] = acc[mt * 4 + nt][3];
        }
    __syncthreads();

    // ---- bias + coalesced store + fused argmax (thread owns one batch b)
    const int b  = tid >> 2;
    const int cg = tid & 3;
    float* orow = out + (size_t)b * (TSTEPS * VOCAB) + (size_t)t * VOCAB + v0;
    float bestv = -3.4e38f;
    int   bestn = 0;
    #pragma unroll
    for (int i = 0; i < 16; i++) {
        int mm = cg * 4 + i * 16;
        float4 v  = *(const float4*)(Ds + b * 260 + mm);
        float4 bi = *(const float4*)(fc_b + v0 + mm);
        float r0 = v.x + bi.x, r1 = v.y + bi.y, r2 = v.z + bi.z, r3 = v.w + bi.w;
        *(float4*)(orow + mm) = make_float4(r0, r1, r2, r3);
        if (r0 > bestv) { bestv = r0; bestn = v0 + mm;     }
        if (r1 > bestv) { bestv = r1; bestn = v0 + mm + 1; }
        if (r2 > bestv) { bestv = r2; bestn = v0 + mm + 2; }
        if (r3 > bestv) { bestv = r3; bestn = v0 + mm + 3; }
    }
    unsigned long long key =
        ((unsigned long long)ford(bestv) << 32) | (unsigned)(~bestn);
    #pragma unroll
    for (int off = 1; off < 4; off <<= 1) {
        unsigned long long ok = __shfl_xor_sync(0xffffffffu, key, off);
        if (ok > key) key = ok;
    }
    if (cg == 0) atomicMax(&g_amax[t * BATCH + b], key);
}

// ---------------- launch ----------------
extern "C" void kernel_launch(void* const* d_in, const int* in_sizes, int n_in,
                              void* d_out, int out_size) {
    const float* hidden    = (const float*)d_in[0];
    const float* cell      = (const float*)d_in[1];
    /* d_in[2] = max_length (compile-time TSTEPS) */
    const int*   start_tok = (const int*)d_in[3];
    const float* embedding = (const float*)d_in[4];
    const float* w_ih      = (const float*)d_in[5];
    const float* w_hh      = (const float*)d_in[6];
    const float* b_ih      = (const float*)d_in[7];
    const float* b_hh      = (const float*)d_in[8];
    const float* fc_w      = (const float*)d_in[9];
    const float* fc_b      = (const float*)d_in[10];
    float* out = (float*)d_out;

    cudaFuncSetAttribute(fc_tc_kernel,
                         cudaFuncAttributeMaxDynamicSharedMemorySize, FC_SMEM);
    cudaFuncSetAttribute(lstm_step_kernel,
                         cudaFuncAttributeMaxDynamicSharedMemorySize, LSTM_SMEM);

    init_kernel<<<128, 256>>>(hidden, cell);
    split_w_kernel<<<VOCAB * HIDDEN / (256 * 4), 256>>>(fc_w);
    for (int t = 0; t < TSTEPS; t++) {
        lstm_step_kernel<<<dim3(64, 2), 1024, LSTM_SMEM>>>(
            embedding, w_ih, w_hh, b_ih, b_hh, start_tok, t);
        fc_tc_kernel<<<VOCAB / 256, 256, FC_SMEM>>>(fc_b, out, t);
    }
}

// round 14
// speedup vs baseline: 3.0013x; 1.0170x over previous
#include <cuda_runtime.h>
#include <cuda_bf16.h>
#include <cstdint>

#define VOCAB  32000
#define EMBED  512
#define HIDDEN 512
#define BATCH  64
#define TSTEPS 64

// -------- persistent scratch (no allocs allowed) --------
__device__ float g_h[2][BATCH * HIDDEN];
__device__ float g_c[BATCH * HIDDEN];
__device__ unsigned long long g_amax[TSTEPS * BATCH];
// bf16 2-way splits: value = sp0 + sp1
__device__ alignas(16) __nv_bfloat16 g_wsp[2][VOCAB * HIDDEN];
__device__ alignas(16) __nv_bfloat16 g_hsp[2][BATCH * HIDDEN];

// monotone float -> uint mapping for atomicMax-based argmax
__device__ __forceinline__ unsigned int ford(float f) {
    unsigned int u = __float_as_uint(f);
    return (u & 0x80000000u) ? ~u : (u | 0x80000000u);
}
__device__ __forceinline__ void split2(float v, __nv_bfloat16& a, __nv_bfloat16& b) {
    a = __float2bfloat16(v);
    b = __float2bfloat16(v - __bfloat162float(a));
}
__device__ __forceinline__ uint32_t smem_u32(const void* p) {
    uint32_t a;
    asm("{ .reg .u64 t; cvta.to.shared.u64 t, %1; cvt.u32.u64 %0, t; }"
        : "=r"(a) : "l"(p));
    return a;
}
__device__ __forceinline__ void ldsm4(uint32_t* r, uint32_t addr) {
    asm volatile("ldmatrix.sync.aligned.m8n8.x4.shared.b16 {%0,%1,%2,%3}, [%4];"
                 : "=r"(r[0]), "=r"(r[1]), "=r"(r[2]), "=r"(r[3]) : "r"(addr));
}
__device__ __forceinline__ void mma16816(float* d, const uint32_t* a, const uint32_t* b) {
    asm volatile(
        "mma.sync.aligned.m16n8k16.row.col.f32.bf16.bf16.f32 "
        "{%0,%1,%2,%3}, {%4,%5,%6,%7}, {%8,%9}, {%0,%1,%2,%3};"
        : "+f"(d[0]), "+f"(d[1]), "+f"(d[2]), "+f"(d[3])
        : "r"(a[0]), "r"(a[1]), "r"(a[2]), "r"(a[3]), "r"(b[0]), "r"(b[1]));
}
__device__ __forceinline__ void cpasync16(uint32_t dst, const void* src) {
    asm volatile("cp.async.cg.shared.global [%0], [%1], 16;"
                 :: "r"(dst), "l"((const void*)__cvta_generic_to_global(src))
                 : "memory");
}
__device__ __forceinline__ void cp_commit() {
    asm volatile("cp.async.commit_group;" ::: "memory");
}

// ---------------- init ----------------
__global__ void init_kernel(const float* __restrict__ hidden,
                            const float* __restrict__ cell) {
    int i = blockIdx.x * blockDim.x + threadIdx.x;
    if (i < BATCH * HIDDEN) {
        g_h[0][i] = hidden[i];
        g_c[i]    = cell[i];
    }
    if (i < TSTEPS * BATCH) g_amax[i] = 0ull;
}

// ---------------- split fc_w into 2 bf16 components (once) ----------------
__global__ __launch_bounds__(256) void split_w_kernel(const float* __restrict__ fc_w) {
    int i0 = (blockIdx.x * 256 + threadIdx.x) * 4;
    if (i0 >= VOCAB * HIDDEN) return;
    float4 v = *(const float4*)(fc_w + i0);
    float vv[4] = {v.x, v.y, v.z, v.w};
    #pragma unroll
    for (int j = 0; j < 4; j++) {
        __nv_bfloat16 a, b;
        split2(vv[j], a, b);
        g_wsp[0][i0 + j] = a;
        g_wsp[1][i0 + j] = b;
    }
}

// ---------------- LSTM step: 1024 thr, 4-way k-split, double-buffered ------
// grid (64, 2). dynamic smem layout (bytes):
//   As [2][128][33] f32 @0       (33792)
//   Ws [2][128][36] f32 @33792   (36864)
//   pacc [3][256] float4 @70656  (12288)
//   toks [32] int @82944
//   sc [32][8] f32 @83072 (old c in, new c out)
//   sh [32][8] f32 @84096
#define LSTM_SMEM 85120

__global__ __launch_bounds__(1024) void lstm_step_kernel(
    const float* __restrict__ embedding,
    const float* __restrict__ w_ih,
    const float* __restrict__ w_hh,
    const float* __restrict__ b_ih,
    const float* __restrict__ b_hh,
    const int*   __restrict__ start_tok,
    int t)
{
    extern __shared__ char lsm[];
    float*  As   = (float*)lsm;               // [2][128][33]
    float*  Ws   = (float*)(lsm + 33792);     // [2][128][36]
    float4* pacc = (float4*)(lsm + 70656);    // [3][256]
    int*    toks = (int*)(lsm + 82944);
    float*  sc   = (float*)(lsm + 83072);     // [32][8]
    float*  sh   = (float*)(lsm + 84096);     // [32][8]

    const int tid = threadIdx.x;
    const int bx  = blockIdx.x;
    const int by  = blockIdx.y;
    const int j0  = bx * 8;
    const int rb  = t & 1, wb = rb ^ 1;

    if (tid < 32) {
        if (t == 0) toks[tid] = *start_tok;
        else {
            unsigned long long key = g_amax[(t - 1) * BATCH + by * 32 + tid];
            toks[tid] = (int)(~((unsigned int)(key & 0xFFFFFFFFull)));
        }
    }
    if (tid < 256) {   // coalesced old-c preload: 8 lanes -> 32B contiguous
        int b = tid >> 3, u = tid & 7;
        sc[tid] = g_c[(by * 32 + b) * HIDDEN + j0 + u];
    }
    __syncthreads();

    const int kh   = tid >> 8;
    const int htid = tid & 255;
    const int m    = htid & 31;
    const int q    = htid >> 5;

    const int lb  = tid & 31;
    const int ks4 = (tid >> 5) * 4;
    const int R   = (lb & 3) * HIDDEN + j0 + (lb >> 2);

    auto ldgA = [&](int kc) -> float4 {
        const int kbase = kc * 128;
        const float* src = (kbase < EMBED)
            ? embedding + (size_t)toks[lb] * EMBED + kbase + ks4
            : g_h[rb] + (by * 32 + lb) * HIDDEN + (kbase - EMBED) + ks4;
        return *(const float4*)src;
    };
    auto ldgW = [&](int kc) -> float4 {
        const int kbase = kc * 128;
        const float* src = (kbase < EMBED)
            ? w_ih + (size_t)R * EMBED + kbase + ks4
            : w_hh + (size_t)R * HIDDEN + (kbase - EMBED) + ks4;
        return *(const float4*)src;
    };
    auto stsAW = [&](int buf, float4 va, float4 vw) {
        float* ap = As + (size_t)(buf * 128 + ks4) * 33 + lb;
        ap[0] = va.x; ap[33] = va.y; ap[66] = va.z; ap[99] = va.w;
        float* wp = Ws + (size_t)(buf * 128 + ks4) * 36 + lb;
        wp[0] = vw.x; wp[36] = vw.y; wp[72] = vw.z; wp[108] = vw.w;
    };

    float acc0 = 0.f, acc1 = 0.f, acc2 = 0.f, acc3 = 0.f;

    {
        float4 va = ldgA(0), vw = ldgW(0);
        stsAW(0, va, vw);
    }
    __syncthreads();

    for (int kc = 0; kc < 8; kc++) {
        const int buf = kc & 1;
        float4 va, vw;
        if (kc < 7) { va = ldgA(kc + 1); vw = ldgW(kc + 1); }

        const int k0 = buf * 128 + kh * 32;
        #pragma unroll
        for (int k = 0; k < 32; k++) {
            float  a = As[(size_t)(k0 + k) * 33 + m];
            float4 w = *(const float4*)&Ws[(size_t)(k0 + k) * 36 + q * 4];
            acc0 += a * w.x; acc1 += a * w.y; acc2 += a * w.z; acc3 += a * w.w;
        }

        if (kc < 7) stsAW(buf ^ 1, va, vw);
        __syncthreads();
    }

    if (kh > 0) pacc[(kh - 1) * 256 + htid] = make_float4(acc0, acc1, acc2, acc3);
    __syncthreads();

    if (kh == 0) {
        #pragma unroll
        for (int p = 0; p < 3; p++) {
            float4 v = pacc[p * 256 + htid];
            acc0 += v.x; acc1 += v.y; acc2 += v.z; acc3 += v.w;
        }
        const int unit = j0 + q;
        acc0 += b_ih[0 * HIDDEN + unit] + b_hh[0 * HIDDEN + unit];
        acc1 += b_ih[1 * HIDDEN + unit] + b_hh[1 * HIDDEN + unit];
        acc2 += b_ih[2 * HIDDEN + unit] + b_hh[2 * HIDDEN + unit];
        acc3 += b_ih[3 * HIDDEN + unit] + b_hh[3 * HIDDEN + unit];

        float ig = 1.f / (1.f + expf(-acc0));
        float fg = 1.f / (1.f + expf(-acc1));
        float gg = tanhf(acc2);
        float og = 1.f / (1.f + expf(-acc3));

        const int slot = m * 8 + q;
        float c = fg * sc[slot] + ig * gg;     // sc holds old c
        float hv = og * tanhf(c);
        sc[slot] = c;                          // stage new c
        sh[slot] = hv;
    }
    __syncthreads();

    if (tid < 256) {   // coalesced writeback: c, h, hsp0, hsp1
        int b = tid >> 3, u = tid & 7;
        const int ci = (by * 32 + b) * HIDDEN + j0 + u;
        float c  = sc[tid];
        float hv = sh[tid];
        g_c[ci] = c;
        g_h[wb][ci] = hv;
        __nv_bfloat16 h0, h1;
        split2(hv, h0, h1);
        g_hsp[0][ci] = h0;
        g_hsp[1][ci] = h1;
    }
}

// ---------------- fc: HMMA bf16x2-split GEMM, Mtile=256, 512 thr 4x4 warps --
// 512 thr / 16 warps, tile [256v x 64b], K in 8 chunks of 64, grid 125 (1/SM).
// warp (wm, wn): wm = wid&3 -> 64 m rows, wn = wid>>2 -> 16 batches.
// stage (80KB): W 2 x [256 x 128B] @0, H 2 x [64 x 128B] @65536.
// two stages = 160KB dynamic; epilogue reuses smem as Ds[64][260] f32.
#define FC_STAGE 81920
#define FC_SMEM  163840

__global__ void __launch_bounds__(512, 1) fc_tc_kernel(
    const float* __restrict__ fc_b, float* __restrict__ out, int t)
{
    extern __shared__ char smem[];
    const int tid  = threadIdx.x;
    const int wid  = tid >> 5;
    const int lane = tid & 31;
    const int wm   = wid & 3;          // m block (64 rows)
    const int wn   = wid >> 2;         // n block (16 batches)
    const int v0   = blockIdx.x * 256;
    const uint32_t sbase = smem_u32(smem);

    auto load_chunk = [&](int ck, int buf) {
        const uint32_t sb = sbase + buf * FC_STAGE;
        #pragma unroll
        for (int s = 0; s < 2; s++) {
            const char* srcb = (const char*)(g_wsp[s] + (size_t)v0 * HIDDEN + ck * 64);
            #pragma unroll
            for (int i = 0; i < 4; i++) {
                int idx = tid + i * 512;           // 0..2047
                int r = idx >> 3, u = idx & 7;     // r 0..255
                cpasync16(sb + s * 32768 + r * 128 + ((u ^ (r & 7)) << 4),
                          srcb + (size_t)r * 1024 + u * 16);
            }
        }
        #pragma unroll
        for (int s = 0; s < 2; s++) {
            const char* srcb = (const char*)(g_hsp[s] + ck * 64);
            {
                int idx = tid;                     // 0..511
                int r = idx >> 3, u = idx & 7;
                cpasync16(sb + 65536 + s * 8192 + r * 128 + ((u ^ (r & 7)) << 4),
                          srcb + (size_t)r * 1024 + u * 16);
            }
        }
        cp_commit();
    };

    float acc[8][4];   // [mt*2 + nt][frag], mt 0..3, nt 0..1
    #pragma unroll
    for (int i = 0; i < 8; i++)
        acc[i][0] = acc[i][1] = acc[i][2] = acc[i][3] = 0.f;

    load_chunk(0, 0);

    for (int ck = 0; ck < 8; ck++) {
        if (ck < 7) load_chunk(ck + 1, (ck + 1) & 1);
        if (ck < 7) asm volatile("cp.async.wait_group 1;" ::: "memory");
        else        asm volatile("cp.async.wait_group 0;" ::: "memory");
        __syncthreads();

        const uint32_t sW = sbase + (ck & 1) * FC_STAGE;
        const uint32_t sH = sW + 65536;

        #pragma unroll
        for (int ks = 0; ks < 4; ks++) {
            uint32_t a0[16], a1[16];
            #pragma unroll
            for (int mt = 0; mt < 4; mt++) {
                int row = wm * 64 + mt * 16 + (lane & 15);
                int u   = (ks << 1) + (lane >> 4);
                uint32_t addr = sW + row * 128 + ((u ^ (row & 7)) << 4);
                ldsm4(&a0[mt * 4], addr);
                ldsm4(&a1[mt * 4], addr + 32768);
            }
            uint32_t b0[4], b1[4];
            {
                int n = wn * 16 + ((lane >> 4) << 3) + (lane & 7);
                int u = (ks << 1) + ((lane >> 3) & 1);
                uint32_t addr = sH + n * 128 + ((u ^ (n & 7)) << 4);
                ldsm4(b0, addr);
                ldsm4(b1, addr + 8192);
            }
            #pragma unroll
            for (int mt = 0; mt < 4; mt++)
                #pragma unroll
                for (int nt = 0; nt < 2; nt++) {
                    mma16816(acc[mt * 2 + nt], &a0[mt * 4], &b0[nt * 2]);
                    mma16816(acc[mt * 2 + nt], &a0[mt * 4], &b1[nt * 2]);
                    mma16816(acc[mt * 2 + nt], &a1[mt * 4], &b0[nt * 2]);
                }
        }
        __syncthreads();
    }

    // ---- stage D to smem transposed: Ds[b][m], pitch 260
    float* Ds = (float*)smem;
    #pragma unroll
    for (int mt = 0; mt < 4; mt++)
        #pragma unroll
        for (int nt = 0; nt < 2; nt++) {
            int bb = wn * 16 + nt * 8 + ((lane & 3) << 1);
            int mm = wm * 64 + mt * 16 + (lane >> 2);
            float* p = Ds + bb * 260 + mm;
            p[0]   = acc[mt * 2 + nt][0];
            p[260] = acc[mt * 2 + nt][1];
            p[8]   = acc[mt * 2 + nt][2];
            p[268] = acc[mt * 2 + nt][3];
        }
    __syncthreads();

    // ---- bias + coalesced store + fused argmax (8 threads per batch b)
    const int b  = tid >> 3;
    const int cg = tid & 7;
    float* orow = out + (size_t)b * (TSTEPS * VOCAB) + (size_t)t * VOCAB + v0;
    float bestv = -3.4e38f;
    int   bestn = 0;
    #pragma unroll
    for (int i = 0; i < 8; i++) {
        int mm = cg * 4 + i * 32;
        float4 v  = *(const float4*)(Ds + b * 260 + mm);
        float4 bi = *(const float4*)(fc_b + v0 + mm);
        float r0 = v.x + bi.x, r1 = v.y + bi.y, r2 = v.z + bi.z, r3 = v.w + bi.w;
        *(float4*)(orow + mm) = make_float4(r0, r1, r2, r3);
        if (r0 > bestv) { bestv = r0; bestn = v0 + mm;     }
        if (r1 > bestv) { bestv = r1; bestn = v0 + mm + 1; }
        if (r2 > bestv) { bestv = r2; bestn = v0 + mm + 2; }
        if (r3 > bestv) { bestv = r3; bestn = v0 + mm + 3; }
    }
    unsigned long long key =
        ((unsigned long long)ford(bestv) << 32) | (unsigned)(~bestn);
    #pragma unroll
    for (int off = 1; off < 8; off <<= 1) {
        unsigned long long ok = __shfl_xor_sync(0xffffffffu, key, off);
        if (ok > key) key = ok;
    }
    if (cg == 0) atomicMax(&g_amax[t * BATCH + b], key);
}

// ---------------- launch ----------------
extern "C" void kernel_launch(void* const* d_in, const int* in_sizes, int n_in,
                              void* d_out, int out_size) {
    const float* hidden    = (const float*)d_in[0];
    const float* cell      = (const float*)d_in[1];
    /* d_in[2] = max_length (compile-time TSTEPS) */
    const int*   start_tok = (const int*)d_in[3];
    const float* embedding = (const float*)d_in[4];
    const float* w_ih      = (const float*)d_in[5];
    const float* w_hh      = (const float*)d_in[6];
    const float* b_ih      = (const float*)d_in[7];
    const float* b_hh      = (const float*)d_in[8];
    const float* fc_w      = (const float*)d_in[9];
    const float* fc_b      = (const float*)d_in[10];
    float* out = (float*)d_out;

    cudaFuncSetAttribute(fc_tc_kernel,
                         cudaFuncAttributeMaxDynamicSharedMemorySize, FC_SMEM);
    cudaFuncSetAttribute(lstm_step_kernel,
                         cudaFuncAttributeMaxDynamicSharedMemorySize, LSTM_SMEM);

    init_kernel<<<128, 256>>>(hidden, cell);
    split_w_kernel<<<VOCAB * HIDDEN / (256 * 4), 256>>>(fc_w);
    for (int t = 0; t < TSTEPS; t++) {
        lstm_step_kernel<<<dim3(64, 2), 1024, LSTM_SMEM>>>(
            embedding, w_ih, w_hh, b_ih, b_hh, start_tok, t);
        fc_tc_kernel<<<VOCAB / 256, 512, FC_SMEM>>>(fc_b, out, t);
    }
}

// round 15
// speedup vs baseline: 3.8384x; 1.2789x over previous
#include <cuda_runtime.h>
#include <cuda_bf16.h>
#include <cstdint>

#define VOCAB  32000
#define EMBED  512
#define HIDDEN 512
#define BATCH  64
#define TSTEPS 64
#define KLSTM  1024          // EMBED + HIDDEN

// -------- persistent scratch (no allocs allowed) --------
__device__ float g_c[BATCH * HIDDEN];
__device__ unsigned long long g_amax[TSTEPS * BATCH];
// bf16 2-way splits: value = sp0 + sp1
__device__ alignas(16) __nv_bfloat16 g_wsp[2][VOCAB * HIDDEN];          // fc_w
__device__ alignas(16) __nv_bfloat16 g_hsp[2][2][BATCH * HIDDEN];       // [phase][split]
__device__ alignas(16) __nv_bfloat16 g_esp[2][VOCAB * EMBED];           // embedding
__device__ alignas(16) __nv_bfloat16 g_lwsp[2][4 * HIDDEN * KLSTM];     // permuted lstm W
__device__ float g_bp[4 * HIDDEN];                                      // permuted bias

__device__ __forceinline__ unsigned int ford(float f) {
    unsigned int u = __float_as_uint(f);
    return (u & 0x80000000u) ? ~u : (u | 0x80000000u);
}
__device__ __forceinline__ void split2(float v, __nv_bfloat16& a, __nv_bfloat16& b) {
    a = __float2bfloat16(v);
    b = __float2bfloat16(v - __bfloat162float(a));
}
__device__ __forceinline__ uint32_t smem_u32(const void* p) {
    uint32_t a;
    asm("{ .reg .u64 t; cvta.to.shared.u64 t, %1; cvt.u32.u64 %0, t; }"
        : "=r"(a) : "l"(p));
    return a;
}
__device__ __forceinline__ void ldsm4(uint32_t* r, uint32_t addr) {
    asm volatile("ldmatrix.sync.aligned.m8n8.x4.shared.b16 {%0,%1,%2,%3}, [%4];"
                 : "=r"(r[0]), "=r"(r[1]), "=r"(r[2]), "=r"(r[3]) : "r"(addr));
}
__device__ __forceinline__ void mma16816(float* d, const uint32_t* a, const uint32_t* b) {
    asm volatile(
        "mma.sync.aligned.m16n8k16.row.col.f32.bf16.bf16.f32 "
        "{%0,%1,%2,%3}, {%4,%5,%6,%7}, {%8,%9}, {%0,%1,%2,%3};"
        : "+f"(d[0]), "+f"(d[1]), "+f"(d[2]), "+f"(d[3])
        : "r"(a[0]), "r"(a[1]), "r"(a[2]), "r"(a[3]), "r"(b[0]), "r"(b[1]));
}
__device__ __forceinline__ void cpasync16(uint32_t dst, const void* src) {
    asm volatile("cp.async.cg.shared.global [%0], [%1], 16;"
                 :: "r"(dst), "l"((const void*)__cvta_generic_to_global(src))
                 : "memory");
}
__device__ __forceinline__ void cp_commit() {
    asm volatile("cp.async.commit_group;" ::: "memory");
}
__device__ __forceinline__ float sigf(float x) { return 1.f / (1.f + expf(-x)); }

// ---------------- init: c, initial-h splits (phase 0), amax ----------------
__global__ void init_kernel(const float* __restrict__ hidden,
                            const float* __restrict__ cell) {
    int i = blockIdx.x * blockDim.x + threadIdx.x;
    if (i < BATCH * HIDDEN) {
        g_c[i] = cell[i];
        __nv_bfloat16 a, b;
        split2(hidden[i], a, b);
        g_hsp[0][0][i] = a;
        g_hsp[0][1][i] = b;
    }
    if (i < TSTEPS * BATCH) g_amax[i] = 0ull;
}

// ---------------- split fc_w ----------------
__global__ __launch_bounds__(256) void split_w_kernel(const float* __restrict__ fc_w) {
    int i0 = (blockIdx.x * 256 + threadIdx.x) * 4;
    if (i0 >= VOCAB * HIDDEN) return;
    float4 v = *(const float4*)(fc_w + i0);
    float vv[4] = {v.x, v.y, v.z, v.w};
    #pragma unroll
    for (int j = 0; j < 4; j++) {
        __nv_bfloat16 a, b;
        split2(vv[j], a, b);
        g_wsp[0][i0 + j] = a;
        g_wsp[1][i0 + j] = b;
    }
}

// ---------------- split embedding ----------------
__global__ __launch_bounds__(256) void split_emb_kernel(const float* __restrict__ emb) {
    int i0 = (blockIdx.x * 256 + threadIdx.x) * 4;
    if (i0 >= VOCAB * EMBED) return;
    float4 v = *(const float4*)(emb + i0);
    float vv[4] = {v.x, v.y, v.z, v.w};
    #pragma unroll
    for (int j = 0; j < 4; j++) {
        __nv_bfloat16 a, b;
        split2(vv[j], a, b);
        g_esp[0][i0 + j] = a;
        g_esp[1][i0 + j] = b;
    }
}

// ---------------- split + permute lstm weights, combined bias ----------------
// dest row r' = unit*4 + gate ; k: 0..511 = w_ih row, 512..1023 = w_hh row.
__global__ __launch_bounds__(256) void split_lstm_w_kernel(
    const float* __restrict__ w_ih, const float* __restrict__ w_hh,
    const float* __restrict__ b_ih, const float* __restrict__ b_hh) {
    int i0 = (blockIdx.x * 256 + threadIdx.x) * 4;
    if (i0 >= 4 * HIDDEN * KLSTM) return;
    int rp = i0 >> 10;          // 0..2047
    int k  = i0 & 1023;
    int unit = rp >> 2, gate = rp & 3;
    int srow = gate * HIDDEN + unit;
    const float* src = (k < EMBED)
        ? w_ih + (size_t)srow * EMBED + k
        : w_hh + (size_t)srow * HIDDEN + (k - EMBED);
    float4 v = *(const float4*)src;
    float vv[4] = {v.x, v.y, v.z, v.w};
    #pragma unroll
    for (int j = 0; j < 4; j++) {
        __nv_bfloat16 a, b;
        split2(vv[j], a, b);
        g_lwsp[0][i0 + j] = a;
        g_lwsp[1][i0 + j] = b;
    }
    if (k == 0) g_bp[rp] = b_ih[srow] + b_hh[srow];
}

// ---------------- LSTM step: HMMA gates GEMM + fused cell update -----------
// 32 CTAs x 256 thr (8 warps: wm = wid&3 -> 16 gate-rows, wn = wid>>2 -> 32 b).
// Tile [64 gate-rows x 64 batch], K=1024 in 16 chunks of 64, double-buffered.
// smem: stage buf*32768: Wp s0 @0, s1 @8192; X s0 @16384, s1 @24576.
//       toks @65536 (64 int), sbias @65792 (64 f32). Epilogue Ds[64][68] @0.
#define LW_SMEM 66048

__global__ void __launch_bounds__(256, 1) lstm_mma_kernel(
    const int* __restrict__ start_tok, int t)
{
    extern __shared__ char lsm[];
    const uint32_t sbase = smem_u32(lsm);
    int*   toks  = (int*)(lsm + 65536);
    float* sbias = (float*)(lsm + 65792);

    const int tid  = threadIdx.x;
    const int wid  = tid >> 5;
    const int lane = tid & 31;
    const int wm   = wid & 3;
    const int wn   = wid >> 2;
    const int bx   = blockIdx.x;        // units bx*16 .. +15
    const int rp_  = t & 1;             // hsp read phase
    const int wp_  = rp_ ^ 1;           // hsp write phase

    if (tid < 64) {
        if (t == 0) toks[tid] = *start_tok;
        else {
            unsigned long long key = g_amax[(t - 1) * BATCH + tid];
            toks[tid] = (int)(~((unsigned int)(key & 0xFFFFFFFFull)));
        }
        sbias[tid] = g_bp[bx * 64 + tid];
    }
    __syncthreads();

    auto load_chunk = [&](int kc, int buf) {
        const uint32_t sb = sbase + buf * 32768;
        #pragma unroll
        for (int s = 0; s < 2; s++) {   // Wp: rows = 64 gate-rows
            const char* srcb = (const char*)(g_lwsp[s]
                             + (size_t)(bx * 64) * KLSTM + kc * 64);
            #pragma unroll
            for (int i = 0; i < 2; i++) {
                int idx = tid + i * 256;
                int r = idx >> 3, u = idx & 7;
                cpasync16(sb + s * 8192 + r * 128 + ((u ^ (r & 7)) << 4),
                          srcb + (size_t)r * 2048 + u * 16);
            }
        }
        #pragma unroll
        for (int s = 0; s < 2; s++) {   // X: rows = 64 batches
            #pragma unroll
            for (int i = 0; i < 2; i++) {
                int idx = tid + i * 256;
                int r = idx >> 3, u = idx & 7;
                const char* src = (kc < 8)
                    ? (const char*)(g_esp[s] + (size_t)toks[r] * EMBED + kc * 64)
                    : (const char*)(g_hsp[rp_][s] + (size_t)r * HIDDEN + (kc - 8) * 64);
                cpasync16(sb + 16384 + s * 8192 + r * 128 + ((u ^ (r & 7)) << 4),
                          src + u * 16);
            }
        }
        cp_commit();
    };

    float acc[4][4];
    #pragma unroll
    for (int i = 0; i < 4; i++)
        acc[i][0] = acc[i][1] = acc[i][2] = acc[i][3] = 0.f;

    load_chunk(0, 0);

    for (int kc = 0; kc < 16; kc++) {
        if (kc < 15) load_chunk(kc + 1, (kc + 1) & 1);
        if (kc < 15) asm volatile("cp.async.wait_group 1;" ::: "memory");
        else         asm volatile("cp.async.wait_group 0;" ::: "memory");
        __syncthreads();

        const uint32_t sW = sbase + (kc & 1) * 32768;
        const uint32_t sX = sW + 16384;

        #pragma unroll
        for (int ks = 0; ks < 4; ks++) {
            uint32_t a0[4], a1[4];
            {
                int row = wm * 16 + (lane & 15);
                int u   = (ks << 1) + (lane >> 4);
                uint32_t addr = sW + row * 128 + ((u ^ (row & 7)) << 4);
                ldsm4(a0, addr);
                ldsm4(a1, addr + 8192);
            }
            uint32_t b0[8], b1[8];
            #pragma unroll
            for (int g = 0; g < 2; g++) {
                int n = wn * 32 + g * 16 + ((lane >> 4) << 3) + (lane & 7);
                int u = (ks << 1) + ((lane >> 3) & 1);
                uint32_t addr = sX + n * 128 + ((u ^ (n & 7)) << 4);
                ldsm4(&b0[g * 4], addr);
                ldsm4(&b1[g * 4], addr + 8192);
            }
            #pragma unroll
            for (int nt = 0; nt < 4; nt++) {
                mma16816(acc[nt], a0, &b0[nt * 2]);
                mma16816(acc[nt], a0, &b1[nt * 2]);
                mma16816(acc[nt], a1, &b0[nt * 2]);
            }
        }
        __syncthreads();
    }

    // ---- stage gates to smem transposed: Ds[b][r], pitch 68
    float* Ds = (float*)lsm;
    #pragma unroll
    for (int nt = 0; nt < 4; nt++) {
        int bb = wn * 32 + nt * 8 + ((lane & 3) << 1);
        int rr = wm * 16 + (lane >> 2);
        float* p = Ds + bb * 68 + rr;
        p[0]      = acc[nt][0];
        p[68]     = acc[nt][1];
        p[8]      = acc[nt][2];
        p[76]     = acc[nt][3];
    }
    __syncthreads();

    // ---- cell update: thread -> (batch b, 4 units)
    {
        const int b  = tid >> 2;
        const int ug = tid & 3;
        const int jb = ug * 4;                 // local units jb..jb+3
        const int ci = b * HIDDEN + bx * 16 + jb;
        float4 cold = *(const float4*)&g_c[ci];
        float co[4];
        float hs0[4], hs1[4];
        #pragma unroll
        for (int j = 0; j < 4; j++) {
            int r = (jb + j) * 4;
            float iv = sigf (Ds[b * 68 + r + 0] + sbias[r + 0]);
            float fv = sigf (Ds[b * 68 + r + 1] + sbias[r + 1]);
            float gv = tanhf(Ds[b * 68 + r + 2] + sbias[r + 2]);
            float ov = sigf (Ds[b * 68 + r + 3] + sbias[r + 3]);
            float cprev = (j == 0) ? cold.x : (j == 1) ? cold.y
                        : (j == 2) ? cold.z : cold.w;
            float c  = fv * cprev + iv * gv;
            float hv = ov * tanhf(c);
            co[j] = c;
            __nv_bfloat16 h0, h1;
            split2(hv, h0, h1);
            hs0[j] = __bfloat162float(h0);     // keep exact bf16 values
            hs1[j] = hv - hs0[j];              // residual pre-round
            // store splits directly below
            ((__nv_bfloat16*)hs0)[0] = h0;     // (unused scratch write guard)
            g_hsp[wp_][0][ci + j] = h0;
            g_hsp[wp_][1][ci + j] = h1;
        }
        *(float4*)&g_c[ci] = make_float4(co[0], co[1], co[2], co[3]);
    }
}

// ---------------- fc: HMMA bf16x2-split GEMM, Mtile=256, 512 thr 4x4 warps --
#define FC_STAGE 81920
#define FC_SMEM  163840

__global__ void __launch_bounds__(512, 1) fc_tc_kernel(
    const float* __restrict__ fc_b, float* __restrict__ out, int t)
{
    extern __shared__ char smem[];
    const int tid  = threadIdx.x;
    const int wid  = tid >> 5;
    const int lane = tid & 31;
    const int wm   = wid & 3;
    const int wn   = wid >> 2;
    const int v0   = blockIdx.x * 256;
    const int ph   = (t & 1) ^ 1;      // hsp phase written by this step's lstm
    const uint32_t sbase = smem_u32(smem);

    auto load_chunk = [&](int ck, int buf) {
        const uint32_t sb = sbase + buf * FC_STAGE;
        #pragma unroll
        for (int s = 0; s < 2; s++) {
            const char* srcb = (const char*)(g_wsp[s] + (size_t)v0 * HIDDEN + ck * 64);
            #pragma unroll
            for (int i = 0; i < 4; i++) {
                int idx = tid + i * 512;
                int r = idx >> 3, u = idx & 7;
                cpasync16(sb + s * 32768 + r * 128 + ((u ^ (r & 7)) << 4),
                          srcb + (size_t)r * 1024 + u * 16);
            }
        }
        #pragma unroll
        for (int s = 0; s < 2; s++) {
            const char* srcb = (const char*)(g_hsp[ph][s] + ck * 64);
            {
                int idx = tid;
                int r = idx >> 3, u = idx & 7;
                cpasync16(sb + 65536 + s * 8192 + r * 128 + ((u ^ (r & 7)) << 4),
                          srcb + (size_t)r * 1024 + u * 16);
            }
        }
        cp_commit();
    };

    float acc[8][4];
    #pragma unroll
    for (int i = 0; i < 8; i++)
        acc[i][0] = acc[i][1] = acc[i][2] = acc[i][3] = 0.f;

    load_chunk(0, 0);

    for (int ck = 0; ck < 8; ck++) {
        if (ck < 7) load_chunk(ck + 1, (ck + 1) & 1);
        if (ck < 7) asm volatile("cp.async.wait_group 1;" ::: "memory");
        else        asm volatile("cp.async.wait_group 0;" ::: "memory");
        __syncthreads();

        const uint32_t sW = sbase + (ck & 1) * FC_STAGE;
        const uint32_t sH = sW + 65536;

        #pragma unroll
        for (int ks = 0; ks < 4; ks++) {
            uint32_t a0[16], a1[16];
            #pragma unroll
            for (int mt = 0; mt < 4; mt++) {
                int row = wm * 64 + mt * 16 + (lane & 15);
                int u   = (ks << 1) + (lane >> 4);
                uint32_t addr = sW + row * 128 + ((u ^ (row & 7)) << 4);
                ldsm4(&a0[mt * 4], addr);
                ldsm4(&a1[mt * 4], addr + 32768);
            }
            uint32_t b0[4], b1[4];
            {
                int n = wn * 16 + ((lane >> 4) << 3) + (lane & 7);
                int u = (ks << 1) + ((lane >> 3) & 1);
                uint32_t addr = sH + n * 128 + ((u ^ (n & 7)) << 4);
                ldsm4(b0, addr);
                ldsm4(b1, addr + 8192);
            }
            #pragma unroll
            for (int mt = 0; mt < 4; mt++)
                #pragma unroll
                for (int nt = 0; nt < 2; nt++) {
                    mma16816(acc[mt * 2 + nt], &a0[mt * 4], &b0[nt * 2]);
                    mma16816(acc[mt * 2 + nt], &a0[mt * 4], &b1[nt * 2]);
                    mma16816(acc[mt * 2 + nt], &a1[mt * 4], &b0[nt * 2]);
                }
        }
        __syncthreads();
    }

    float* Ds = (float*)smem;
    #pragma unroll
    for (int mt = 0; mt < 4; mt++)
        #pragma unroll
        for (int nt = 0; nt < 2; nt++) {
            int bb = wn * 16 + nt * 8 + ((lane & 3) << 1);
            int mm = wm * 64 + mt * 16 + (lane >> 2);
            float* p = Ds + bb * 260 + mm;
            p[0]   = acc[mt * 2 + nt][0];
            p[260] = acc[mt * 2 + nt][1];
            p[8]   = acc[mt * 2 + nt][2];
            p[268] = acc[mt * 2 + nt][3];
        }
    __syncthreads();

    const int b  = tid >> 3;
    const int cg = tid & 7;
    float* orow = out + (size_t)b * (TSTEPS * VOCAB) + (size_t)t * VOCAB + v0;
    float bestv = -3.4e38f;
    int   bestn = 0;
    #pragma unroll
    for (int i = 0; i < 8; i++) {
        int mm = cg * 4 + i * 32;
        float4 v  = *(const float4*)(Ds + b * 260 + mm);
        float4 bi = *(const float4*)(fc_b + v0 + mm);
        float r0 = v.x + bi.x, r1 = v.y + bi.y, r2 = v.z + bi.z, r3 = v.w + bi.w;
        *(float4*)(orow + mm) = make_float4(r0, r1, r2, r3);
        if (r0 > bestv) { bestv = r0; bestn = v0 + mm;     }
        if (r1 > bestv) { bestv = r1; bestn = v0 + mm + 1; }
        if (r2 > bestv) { bestv = r2; bestn = v0 + mm + 2; }
        if (r3 > bestv) { bestv = r3; bestn = v0 + mm + 3; }
    }
    unsigned long long key =
        ((unsigned long long)ford(bestv) << 32) | (unsigned)(~bestn);
    #pragma unroll
    for (int off = 1; off < 8; off <<= 1) {
        unsigned long long ok = __shfl_xor_sync(0xffffffffu, key, off);
        if (ok > key) key = ok;
    }
    if (cg == 0) atomicMax(&g_amax[t * BATCH + b], key);
}

// ---------------- launch ----------------
extern "C" void kernel_launch(void* const* d_in, const int* in_sizes, int n_in,
                              void* d_out, int out_size) {
    const float* hidden    = (const float*)d_in[0];
    const float* cell      = (const float*)d_in[1];
    /* d_in[2] = max_length (compile-time TSTEPS) */
    const int*   start_tok = (const int*)d_in[3];
    const float* embedding = (const float*)d_in[4];
    const float* w_ih      = (const float*)d_in[5];
    const float* w_hh      = (const float*)d_in[6];
    const float* b_ih      = (const float*)d_in[7];
    const float* b_hh      = (const float*)d_in[8];
    const float* fc_w      = (const float*)d_in[9];
    const float* fc_b      = (const float*)d_in[10];
    float* out = (float*)d_out;

    cudaFuncSetAttribute(fc_tc_kernel,
                         cudaFuncAttributeMaxDynamicSharedMemorySize, FC_SMEM);
    cudaFuncSetAttribute(lstm_mma_kernel,
                         cudaFuncAttributeMaxDynamicSharedMemorySize, LW_SMEM);

    init_kernel<<<128, 256>>>(hidden, cell);
    split_w_kernel<<<VOCAB * HIDDEN / 1024, 256>>>(fc_w);
    split_emb_kernel<<<VOCAB * EMBED / 1024, 256>>>(embedding);
    split_lstm_w_kernel<<<4 * HIDDEN * KLSTM / 1024, 256>>>(w_ih, w_hh, b_ih, b_hh);
    for (int t = 0; t < TSTEPS; t++) {
        lstm_mma_kernel<<<32, 256, LW_SMEM>>>(start_tok, t);
        fc_tc_kernel<<<VOCAB / 256, 512, FC_SMEM>>>(fc_b, out, t);
    }
}

// round 16
// speedup vs baseline: 3.8842x; 1.0119x over previous
#include <cuda_runtime.h>
#include <cuda_bf16.h>
#include <cstdint>

#define VOCAB  32000
#define EMBED  512
#define HIDDEN 512
#define BATCH  64
#define TSTEPS 64
#define KLSTM  1024          // EMBED + HIDDEN

// -------- persistent scratch (no allocs allowed) --------
__device__ float g_c[BATCH * HIDDEN];
__device__ unsigned long long g_amax[TSTEPS * BATCH];
// bf16 2-way splits: value = sp0 + sp1
__device__ alignas(16) __nv_bfloat16 g_wsp[2][VOCAB * HIDDEN];          // fc_w
__device__ alignas(16) __nv_bfloat16 g_hsp[2][2][BATCH * HIDDEN];       // [phase][split]
__device__ alignas(16) __nv_bfloat16 g_esp[2][VOCAB * EMBED];           // embedding
__device__ alignas(16) __nv_bfloat16 g_lwsp[2][4 * HIDDEN * KLSTM];     // permuted lstm W
__device__ float g_bp[4 * HIDDEN];                                      // permuted bias

__device__ __forceinline__ unsigned int ford(float f) {
    unsigned int u = __float_as_uint(f);
    return (u & 0x80000000u) ? ~u : (u | 0x80000000u);
}
__device__ __forceinline__ void split2(float v, __nv_bfloat16& a, __nv_bfloat16& b) {
    a = __float2bfloat16(v);
    b = __float2bfloat16(v - __bfloat162float(a));
}
__device__ __forceinline__ uint32_t smem_u32(const void* p) {
    uint32_t a;
    asm("{ .reg .u64 t; cvta.to.shared.u64 t, %1; cvt.u32.u64 %0, t; }"
        : "=r"(a) : "l"(p));
    return a;
}
__device__ __forceinline__ void ldsm4(uint32_t* r, uint32_t addr) {
    asm volatile("ldmatrix.sync.aligned.m8n8.x4.shared.b16 {%0,%1,%2,%3}, [%4];"
                 : "=r"(r[0]), "=r"(r[1]), "=r"(r[2]), "=r"(r[3]) : "r"(addr));
}
__device__ __forceinline__ void mma16816(float* d, const uint32_t* a, const uint32_t* b) {
    asm volatile(
        "mma.sync.aligned.m16n8k16.row.col.f32.bf16.bf16.f32 "
        "{%0,%1,%2,%3}, {%4,%5,%6,%7}, {%8,%9}, {%0,%1,%2,%3};"
        : "+f"(d[0]), "+f"(d[1]), "+f"(d[2]), "+f"(d[3])
        : "r"(a[0]), "r"(a[1]), "r"(a[2]), "r"(a[3]), "r"(b[0]), "r"(b[1]));
}
__device__ __forceinline__ void cpasync16(uint32_t dst, const void* src) {
    asm volatile("cp.async.cg.shared.global [%0], [%1], 16;"
                 :: "r"(dst), "l"((const void*)__cvta_generic_to_global(src))
                 : "memory");
}
__device__ __forceinline__ void cp_commit() {
    asm volatile("cp.async.commit_group;" ::: "memory");
}
__device__ __forceinline__ float sigf(float x) { return 1.f / (1.f + expf(-x)); }
// swizzled offset within a tile of 256B rows (SW128 pattern per 128B half)
__device__ __forceinline__ uint32_t swz256(int r, int u) {
    return r * 256 + ((u >> 3) << 7) + ((((u & 7) ^ (r & 7))) << 4);
}

// ---------------- init: c, initial-h splits (phase 0), amax ----------------
__global__ void init_kernel(const float* __restrict__ hidden,
                            const float* __restrict__ cell) {
    int i = blockIdx.x * blockDim.x + threadIdx.x;
    if (i < BATCH * HIDDEN) {
        g_c[i] = cell[i];
        __nv_bfloat16 a, b;
        split2(hidden[i], a, b);
        g_hsp[0][0][i] = a;
        g_hsp[0][1][i] = b;
    }
    if (i < TSTEPS * BATCH) g_amax[i] = 0ull;
}

// ---------------- split fc_w ----------------
__global__ __launch_bounds__(256) void split_w_kernel(const float* __restrict__ fc_w) {
    int i0 = (blockIdx.x * 256 + threadIdx.x) * 4;
    if (i0 >= VOCAB * HIDDEN) return;
    float4 v = *(const float4*)(fc_w + i0);
    float vv[4] = {v.x, v.y, v.z, v.w};
    #pragma unroll
    for (int j = 0; j < 4; j++) {
        __nv_bfloat16 a, b;
        split2(vv[j], a, b);
        g_wsp[0][i0 + j] = a;
        g_wsp[1][i0 + j] = b;
    }
}

// ---------------- split embedding ----------------
__global__ __launch_bounds__(256) void split_emb_kernel(const float* __restrict__ emb) {
    int i0 = (blockIdx.x * 256 + threadIdx.x) * 4;
    if (i0 >= VOCAB * EMBED) return;
    float4 v = *(const float4*)(emb + i0);
    float vv[4] = {v.x, v.y, v.z, v.w};
    #pragma unroll
    for (int j = 0; j < 4; j++) {
        __nv_bfloat16 a, b;
        split2(vv[j], a, b);
        g_esp[0][i0 + j] = a;
        g_esp[1][i0 + j] = b;
    }
}

// ---------------- split + permute lstm weights, combined bias ----------------
__global__ __launch_bounds__(256) void split_lstm_w_kernel(
    const float* __restrict__ w_ih, const float* __restrict__ w_hh,
    const float* __restrict__ b_ih, const float* __restrict__ b_hh) {
    int i0 = (blockIdx.x * 256 + threadIdx.x) * 4;
    if (i0 >= 4 * HIDDEN * KLSTM) return;
    int rp = i0 >> 10;          // 0..2047
    int k  = i0 & 1023;
    int unit = rp >> 2, gate = rp & 3;
    int srow = gate * HIDDEN + unit;
    const float* src = (k < EMBED)
        ? w_ih + (size_t)srow * EMBED + k
        : w_hh + (size_t)srow * HIDDEN + (k - EMBED);
    float4 v = *(const float4*)src;
    float vv[4] = {v.x, v.y, v.z, v.w};
    #pragma unroll
    for (int j = 0; j < 4; j++) {
        __nv_bfloat16 a, b;
        split2(vv[j], a, b);
        g_lwsp[0][i0 + j] = a;
        g_lwsp[1][i0 + j] = b;
    }
    if (k == 0) g_bp[rp] = b_ih[srow] + b_hh[srow];
}

// ---------------- LSTM step: HMMA gates GEMM, K-chunks of 128 --------------
// 32 CTAs x 256 thr (8 warps: wm = wid&3 -> 16 gate-rows, wn = wid>>2 -> 32 b).
// Tile [64 gate-rows x 64 batch], K=1024 in 8 chunks of 128, double-buffered.
// stage buf*65536: Wp s0 @0 (16KB), s1 @16384; X s0 @32768, s1 @49152.
// toks @131072, sbias @131328. Epilogue Ds[64][68] reuses @0.
#define LW_SMEM 131584

__global__ void __launch_bounds__(256, 1) lstm_mma_kernel(
    const int* __restrict__ start_tok, int t)
{
    extern __shared__ char lsm[];
    const uint32_t sbase = smem_u32(lsm);
    int*   toks  = (int*)(lsm + 131072);
    float* sbias = (float*)(lsm + 131328);

    const int tid  = threadIdx.x;
    const int wid  = tid >> 5;
    const int lane = tid & 31;
    const int wm   = wid & 3;
    const int wn   = wid >> 2;
    const int bx   = blockIdx.x;        // gate-rows bx*64 .. +63
    const int rp_  = t & 1;             // hsp read phase
    const int wp_  = rp_ ^ 1;           // hsp write phase

    if (tid < 64) {
        if (t == 0) toks[tid] = *start_tok;
        else {
            unsigned long long key = g_amax[(t - 1) * BATCH + tid];
            toks[tid] = (int)(~((unsigned int)(key & 0xFFFFFFFFull)));
        }
        sbias[tid] = g_bp[bx * 64 + tid];
    }
    __syncthreads();

    auto load_chunk = [&](int kc, int buf) {   // kc in 0..7, k = kc*128
        const uint32_t sb = sbase + buf * 65536;
        #pragma unroll
        for (int s = 0; s < 2; s++) {   // Wp: 64 gate-rows x 256B
            const char* srcb = (const char*)(g_lwsp[s]
                             + (size_t)(bx * 64) * KLSTM + kc * 128);
            #pragma unroll
            for (int i = 0; i < 4; i++) {
                int idx = tid + i * 256;        // 0..1023
                int r = idx >> 4, u = idx & 15;
                cpasync16(sb + s * 16384 + swz256(r, u),
                          srcb + (size_t)r * 2048 + u * 16);
            }
        }
        #pragma unroll
        for (int s = 0; s < 2; s++) {   // X: 64 batches x 256B
            #pragma unroll
            for (int i = 0; i < 4; i++) {
                int idx = tid + i * 256;
                int r = idx >> 4, u = idx & 15;
                const char* src = (kc < 4)
                    ? (const char*)(g_esp[s] + (size_t)toks[r] * EMBED + kc * 128)
                    : (const char*)(g_hsp[rp_][s] + (size_t)r * HIDDEN + (kc - 4) * 128);
                cpasync16(sb + 32768 + s * 16384 + swz256(r, u),
                          src + u * 16);
            }
        }
        cp_commit();
    };

    float acc[4][4];
    #pragma unroll
    for (int i = 0; i < 4; i++)
        acc[i][0] = acc[i][1] = acc[i][2] = acc[i][3] = 0.f;

    load_chunk(0, 0);

    for (int kc = 0; kc < 8; kc++) {
        if (kc < 7) load_chunk(kc + 1, (kc + 1) & 1);
        if (kc < 7) asm volatile("cp.async.wait_group 1;" ::: "memory");
        else        asm volatile("cp.async.wait_group 0;" ::: "memory");
        __syncthreads();

        const uint32_t sW = sbase + (kc & 1) * 65536;
        const uint32_t sX = sW + 32768;

        #pragma unroll
        for (int ks = 0; ks < 8; ks++) {
            uint32_t a0[4], a1[4];
            {
                int row = wm * 16 + (lane & 15);
                int u   = (ks << 1) + (lane >> 4);
                ldsm4(a0, sW + swz256(row, u));
                ldsm4(a1, sW + 16384 + swz256(row, u));
            }
            uint32_t b0[8], b1[8];
            #pragma unroll
            for (int g = 0; g < 2; g++) {
                int n = wn * 32 + g * 16 + ((lane >> 4) << 3) + (lane & 7);
                int u = (ks << 1) + ((lane >> 3) & 1);
                ldsm4(&b0[g * 4], sX + swz256(n, u));
                ldsm4(&b1[g * 4], sX + 16384 + swz256(n, u));
            }
            #pragma unroll
            for (int nt = 0; nt < 4; nt++) {
                mma16816(acc[nt], a0, &b0[nt * 2]);
                mma16816(acc[nt], a0, &b1[nt * 2]);
                mma16816(acc[nt], a1, &b0[nt * 2]);
            }
        }
        __syncthreads();
    }

    // ---- stage gates to smem transposed: Ds[b][r], pitch 68
    float* Ds = (float*)lsm;
    #pragma unroll
    for (int nt = 0; nt < 4; nt++) {
        int bb = wn * 32 + nt * 8 + ((lane & 3) << 1);
        int rr = wm * 16 + (lane >> 2);
        float* p = Ds + bb * 68 + rr;
        p[0]  = acc[nt][0];
        p[68] = acc[nt][1];
        p[8]  = acc[nt][2];
        p[76] = acc[nt][3];
    }
    __syncthreads();

    // ---- cell update: thread -> (batch b, 4 units)
    {
        const int b  = tid >> 2;
        const int ug = tid & 3;
        const int jb = ug * 4;                 // local units jb..jb+3
        const int ci = b * HIDDEN + bx * 16 + jb;
        float4 cold = *(const float4*)&g_c[ci];
        float co[4];
        #pragma unroll
        for (int j = 0; j < 4; j++) {
            int r = (jb + j) * 4;
            float iv = sigf (Ds[b * 68 + r + 0] + sbias[r + 0]);
            float fv = sigf (Ds[b * 68 + r + 1] + sbias[r + 1]);
            float gv = tanhf(Ds[b * 68 + r + 2] + sbias[r + 2]);
            float ov = sigf (Ds[b * 68 + r + 3] + sbias[r + 3]);
            float cprev = (j == 0) ? cold.x : (j == 1) ? cold.y
                        : (j == 2) ? cold.z : cold.w;
            float c  = fv * cprev + iv * gv;
            float hv = ov * tanhf(c);
            co[j] = c;
            __nv_bfloat16 h0, h1;
            split2(hv, h0, h1);
            g_hsp[wp_][0][ci + j] = h0;
            g_hsp[wp_][1][ci + j] = h1;
        }
        *(float4*)&g_c[ci] = make_float4(co[0], co[1], co[2], co[3]);
    }
}

// ---------------- fc: HMMA bf16x2-split GEMM, Mtile=256, 8m x 2n warps ------
// 512 thr / 16 warps: wm = wid&7 -> 32 m rows, wn = wid>>3 -> 32 batches.
// K in 8 chunks of 64, grid 125 (1/SM).
// stage (80KB): W 2 x [256 x 128B] @0, H 2 x [64 x 128B] @65536.
#define FC_STAGE 81920
#define FC_SMEM  163840

__global__ void __launch_bounds__(512, 1) fc_tc_kernel(
    const float* __restrict__ fc_b, float* __restrict__ out, int t)
{
    extern __shared__ char smem[];
    const int tid  = threadIdx.x;
    const int wid  = tid >> 5;
    const int lane = tid & 31;
    const int wm   = wid & 7;          // m block (32 rows)
    const int wn   = wid >> 3;         // n block (32 batches)
    const int v0   = blockIdx.x * 256;
    const int ph   = (t & 1) ^ 1;      // hsp phase written by this step's lstm
    const uint32_t sbase = smem_u32(smem);

    auto load_chunk = [&](int ck, int buf) {
        const uint32_t sb = sbase + buf * FC_STAGE;
        #pragma unroll
        for (int s = 0; s < 2; s++) {
            const char* srcb = (const char*)(g_wsp[s] + (size_t)v0 * HIDDEN + ck * 64);
            #pragma unroll
            for (int i = 0; i < 4; i++) {
                int idx = tid + i * 512;
                int r = idx >> 3, u = idx & 7;
                cpasync16(sb + s * 32768 + r * 128 + ((u ^ (r & 7)) << 4),
                          srcb + (size_t)r * 1024 + u * 16);
            }
        }
        #pragma unroll
        for (int s = 0; s < 2; s++) {
            const char* srcb = (const char*)(g_hsp[ph][s] + ck * 64);
            {
                int idx = tid;
                int r = idx >> 3, u = idx & 7;
                cpasync16(sb + 65536 + s * 8192 + r * 128 + ((u ^ (r & 7)) << 4),
                          srcb + (size_t)r * 1024 + u * 16);
            }
        }
        cp_commit();
    };

    float acc[8][4];   // [mt*4 + nt], mt 0..1, nt 0..3
    #pragma unroll
    for (int i = 0; i < 8; i++)
        acc[i][0] = acc[i][1] = acc[i][2] = acc[i][3] = 0.f;

    load_chunk(0, 0);

    for (int ck = 0; ck < 8; ck++) {
        if (ck < 7) load_chunk(ck + 1, (ck + 1) & 1);
        if (ck < 7) asm volatile("cp.async.wait_group 1;" ::: "memory");
        else        asm volatile("cp.async.wait_group 0;" ::: "memory");
        __syncthreads();

        const uint32_t sW = sbase + (ck & 1) * FC_STAGE;
        const uint32_t sH = sW + 65536;

        #pragma unroll
        for (int ks = 0; ks < 4; ks++) {
            uint32_t a0[8], a1[8];
            #pragma unroll
            for (int mt = 0; mt < 2; mt++) {
                int row = wm * 32 + mt * 16 + (lane & 15);
                int u   = (ks << 1) + (lane >> 4);
                uint32_t addr = sW + row * 128 + ((u ^ (row & 7)) << 4);
                ldsm4(&a0[mt * 4], addr);
                ldsm4(&a1[mt * 4], addr + 32768);
            }
            uint32_t b0[8], b1[8];
            #pragma unroll
            for (int g = 0; g < 2; g++) {
                int n = wn * 32 + g * 16 + ((lane >> 4) << 3) + (lane & 7);
                int u = (ks << 1) + ((lane >> 3) & 1);
                uint32_t addr = sH + n * 128 + ((u ^ (n & 7)) << 4);
                ldsm4(&b0[g * 4], addr);
                ldsm4(&b1[g * 4], addr + 8192);
            }
            #pragma unroll
            for (int mt = 0; mt < 2; mt++)
                #pragma unroll
                for (int nt = 0; nt < 4; nt++) {
                    mma16816(acc[mt * 4 + nt], &a0[mt * 4], &b0[nt * 2]);
                    mma16816(acc[mt * 4 + nt], &a0[mt * 4], &b1[nt * 2]);
                    mma16816(acc[mt * 4 + nt], &a1[mt * 4], &b0[nt * 2]);
                }
        }
        __syncthreads();
    }

    // ---- stage D to smem transposed: Ds[b][m], pitch 260
    float* Ds = (float*)smem;
    #pragma unroll
    for (int mt = 0; mt < 2; mt++)
        #pragma unroll
        for (int nt = 0; nt < 4; nt++) {
            int bb = wn * 32 + nt * 8 + ((lane & 3) << 1);
            int mm = wm * 32 + mt * 16 + (lane >> 2);
            float* p = Ds + bb * 260 + mm;
            p[0]   = acc[mt * 4 + nt][0];
            p[260] = acc[mt * 4 + nt][1];
            p[8]   = acc[mt * 4 + nt][2];
            p[268] = acc[mt * 4 + nt][3];
        }
    __syncthreads();

    // ---- bias + coalesced store + fused argmax (8 threads per batch b)
    const int b  = tid >> 3;
    const int cg = tid & 7;
    float* orow = out + (size_t)b * (TSTEPS * VOCAB) + (size_t)t * VOCAB + v0;
    float bestv = -3.4e38f;
    int   bestn = 0;
    #pragma unroll
    for (int i = 0; i < 8; i++) {
        int mm = cg * 4 + i * 32;
        float4 v  = *(const float4*)(Ds + b * 260 + mm);
        float4 bi = *(const float4*)(fc_b + v0 + mm);
        float r0 = v.x + bi.x, r1 = v.y + bi.y, r2 = v.z + bi.z, r3 = v.w + bi.w;
        *(float4*)(orow + mm) = make_float4(r0, r1, r2, r3);
        if (r0 > bestv) { bestv = r0; bestn = v0 + mm;     }
        if (r1 > bestv) { bestv = r1; bestn = v0 + mm + 1; }
        if (r2 > bestv) { bestv = r2; bestn = v0 + mm + 2; }
        if (r3 > bestv) { bestv = r3; bestn = v0 + mm + 3; }
    }
    unsigned long long key =
        ((unsigned long long)ford(bestv) << 32) | (unsigned)(~bestn);
    #pragma unroll
    for (int off = 1; off < 8; off <<= 1) {
        unsigned long long ok = __shfl_xor_sync(0xffffffffu, key, off);
        if (ok > key) key = ok;
    }
    if (cg == 0) atomicMax(&g_amax[t * BATCH + b], key);
}

// ---------------- launch ----------------
extern "C" void kernel_launch(void* const* d_in, const int* in_sizes, int n_in,
                              void* d_out, int out_size) {
    const float* hidden    = (const float*)d_in[0];
    const float* cell      = (const float*)d_in[1];
    /* d_in[2] = max_length (compile-time TSTEPS) */
    const int*   start_tok = (const int*)d_in[3];
    const float* embedding = (const float*)d_in[4];
    const float* w_ih      = (const float*)d_in[5];
    const float* w_hh      = (const float*)d_in[6];
    const float* b_ih      = (const float*)d_in[7];
    const float* b_hh      = (const float*)d_in[8];
    const float* fc_w      = (const float*)d_in[9];
    const float* fc_b      = (const float*)d_in[10];
    float* out = (float*)d_out;

    cudaFuncSetAttribute(fc_tc_kernel,
                         cudaFuncAttributeMaxDynamicSharedMemorySize, FC_SMEM);
    cudaFuncSetAttribute(lstm_mma_kernel,
                         cudaFuncAttributeMaxDynamicSharedMemorySize, LW_SMEM);

    init_kernel<<<128, 256>>>(hidden, cell);
    split_w_kernel<<<VOCAB * HIDDEN / 1024, 256>>>(fc_w);
    split_emb_kernel<<<VOCAB * EMBED / 1024, 256>>>(embedding);
    split_lstm_w_kernel<<<4 * HIDDEN * KLSTM / 1024, 256>>>(w_ih, w_hh, b_ih, b_hh);
    for (int t = 0; t < TSTEPS; t++) {
        lstm_mma_kernel<<<32, 256, LW_SMEM>>>(start_tok, t);
        fc_tc_kernel<<<VOCAB / 256, 512, FC_SMEM>>>(fc_b, out, t);
    }
}

// round 17
// speedup vs baseline: 4.3995x; 1.1327x over previous
#include <cuda_runtime.h>
#include <cuda_bf16.h>
#include <cstdint>

#define VOCAB  32000
#define EMBED  512
#define HIDDEN 512
#define BATCH  64
#define TSTEPS 64
#define KLSTM  1024          // EMBED + HIDDEN

// -------- persistent scratch (no allocs allowed) --------
__device__ float g_c[BATCH * HIDDEN];
__device__ unsigned long long g_amax[TSTEPS * BATCH];
__device__ float g_gh[BATCH * 4 * HIDDEN];   // Whh·h partial gates [b][2048]
// bf16 2-way splits: value = sp0 + sp1
__device__ alignas(16) __nv_bfloat16 g_wsp[2][VOCAB * HIDDEN];          // fc_w
__device__ alignas(16) __nv_bfloat16 g_hsp[2][2][BATCH * HIDDEN];       // [phase][split]
__device__ alignas(16) __nv_bfloat16 g_esp[2][VOCAB * EMBED];           // embedding
__device__ alignas(16) __nv_bfloat16 g_lwsp[2][4 * HIDDEN * KLSTM];     // permuted lstm W
__device__ float g_bp[4 * HIDDEN];                                      // permuted bias

__device__ __forceinline__ unsigned int ford(float f) {
    unsigned int u = __float_as_uint(f);
    return (u & 0x80000000u) ? ~u : (u | 0x80000000u);
}
__device__ __forceinline__ void split2(float v, __nv_bfloat16& a, __nv_bfloat16& b) {
    a = __float2bfloat16(v);
    b = __float2bfloat16(v - __bfloat162float(a));
}
__device__ __forceinline__ uint32_t smem_u32(const void* p) {
    uint32_t a;
    asm("{ .reg .u64 t; cvta.to.shared.u64 t, %1; cvt.u32.u64 %0, t; }"
        : "=r"(a) : "l"(p));
    return a;
}
__device__ __forceinline__ void ldsm4(uint32_t* r, uint32_t addr) {
    asm volatile("ldmatrix.sync.aligned.m8n8.x4.shared.b16 {%0,%1,%2,%3}, [%4];"
                 : "=r"(r[0]), "=r"(r[1]), "=r"(r[2]), "=r"(r[3]) : "r"(addr));
}
__device__ __forceinline__ void mma16816(float* d, const uint32_t* a, const uint32_t* b) {
    asm volatile(
        "mma.sync.aligned.m16n8k16.row.col.f32.bf16.bf16.f32 "
        "{%0,%1,%2,%3}, {%4,%5,%6,%7}, {%8,%9}, {%0,%1,%2,%3};"
        : "+f"(d[0]), "+f"(d[1]), "+f"(d[2]), "+f"(d[3])
        : "r"(a[0]), "r"(a[1]), "r"(a[2]), "r"(a[3]), "r"(b[0]), "r"(b[1]));
}
__device__ __forceinline__ void cpasync16(uint32_t dst, const void* src) {
    asm volatile("cp.async.cg.shared.global [%0], [%1], 16;"
                 :: "r"(dst), "l"((const void*)__cvta_generic_to_global(src))
                 : "memory");
}
__device__ __forceinline__ void cp_commit() {
    asm volatile("cp.async.commit_group;" ::: "memory");
}
__device__ __forceinline__ float sigf(float x) { return 1.f / (1.f + expf(-x)); }
// swizzled offset within a tile of 256B rows (SW128 pattern per 128B half)
__device__ __forceinline__ uint32_t swz256(int r, int u) {
    return r * 256 + ((u >> 3) << 7) + ((((u & 7) ^ (r & 7))) << 4);
}

// ---------------- init: c, initial-h splits (phase 0), amax ----------------
__global__ void init_kernel(const float* __restrict__ hidden,
                            const float* __restrict__ cell) {
    int i = blockIdx.x * blockDim.x + threadIdx.x;
    if (i < BATCH * HIDDEN) {
        g_c[i] = cell[i];
        __nv_bfloat16 a, b;
        split2(hidden[i], a, b);
        g_hsp[0][0][i] = a;
        g_hsp[0][1][i] = b;
    }
    if (i < TSTEPS * BATCH) g_amax[i] = 0ull;
}

// ---------------- split fc_w ----------------
__global__ __launch_bounds__(256) void split_w_kernel(const float* __restrict__ fc_w) {
    int i0 = (blockIdx.x * 256 + threadIdx.x) * 4;
    if (i0 >= VOCAB * HIDDEN) return;
    float4 v = *(const float4*)(fc_w + i0);
    float vv[4] = {v.x, v.y, v.z, v.w};
    #pragma unroll
    for (int j = 0; j < 4; j++) {
        __nv_bfloat16 a, b;
        split2(vv[j], a, b);
        g_wsp[0][i0 + j] = a;
        g_wsp[1][i0 + j] = b;
    }
}

// ---------------- split embedding ----------------
__global__ __launch_bounds__(256) void split_emb_kernel(const float* __restrict__ emb) {
    int i0 = (blockIdx.x * 256 + threadIdx.x) * 4;
    if (i0 >= VOCAB * EMBED) return;
    float4 v = *(const float4*)(emb + i0);
    float vv[4] = {v.x, v.y, v.z, v.w};
    #pragma unroll
    for (int j = 0; j < 4; j++) {
        __nv_bfloat16 a, b;
        split2(vv[j], a, b);
        g_esp[0][i0 + j] = a;
        g_esp[1][i0 + j] = b;
    }
}

// ---------------- split + permute lstm weights, combined bias ----------------
__global__ __launch_bounds__(256) void split_lstm_w_kernel(
    const float* __restrict__ w_ih, const float* __restrict__ w_hh,
    const float* __restrict__ b_ih, const float* __restrict__ b_hh) {
    int i0 = (blockIdx.x * 256 + threadIdx.x) * 4;
    if (i0 >= 4 * HIDDEN * KLSTM) return;
    int rp = i0 >> 10;          // 0..2047
    int k  = i0 & 1023;
    int unit = rp >> 2, gate = rp & 3;
    int srow = gate * HIDDEN + unit;
    const float* src = (k < EMBED)
        ? w_ih + (size_t)srow * EMBED + k
        : w_hh + (size_t)srow * HIDDEN + (k - EMBED);
    float4 v = *(const float4*)src;
    float vv[4] = {v.x, v.y, v.z, v.w};
    #pragma unroll
    for (int j = 0; j < 4; j++) {
        __nv_bfloat16 a, b;
        split2(vv[j], a, b);
        g_lwsp[0][i0 + j] = a;
        g_lwsp[1][i0 + j] = b;
    }
    if (k == 0) g_bp[rp] = b_ih[srow] + b_hh[srow];
}

// ---------------- LSTM x-half: embedding GEMM + gh add + cell update -------
// 32 CTAs x 256 thr, tile [64 gate-rows x 64 b], K=512 (embed) in 4 chunks of 128.
// stage buf*65536: Wp s0 @0 (16KB), s1 @16384; X s0 @32768, s1 @49152.
// toks @131072, sbias @131328. Epilogue Ds[64][68] reuses @0.
#define LW_SMEM 131584

__global__ void __launch_bounds__(256, 1) lstm_x_kernel(
    const int* __restrict__ start_tok, int t)
{
    extern __shared__ char lsm[];
    const uint32_t sbase = smem_u32(lsm);
    int*   toks  = (int*)(lsm + 131072);
    float* sbias = (float*)(lsm + 131328);

    const int tid  = threadIdx.x;
    const int wid  = tid >> 5;
    const int lane = tid & 31;
    const int wm   = wid & 3;
    const int wn   = wid >> 2;
    const int bx   = blockIdx.x;        // gate-rows bx*64 .. +63
    const int wp_  = (t & 1) ^ 1;       // hsp write phase

    if (tid < 64) {
        if (t == 0) toks[tid] = *start_tok;
        else {
            unsigned long long key = g_amax[(t - 1) * BATCH + tid];
            toks[tid] = (int)(~((unsigned int)(key & 0xFFFFFFFFull)));
        }
        sbias[tid] = g_bp[bx * 64 + tid];
    }
    __syncthreads();

    auto load_chunk = [&](int kc, int buf) {   // kc in 0..3, k = kc*128 (embed)
        const uint32_t sb = sbase + buf * 65536;
        #pragma unroll
        for (int s = 0; s < 2; s++) {   // Wp: 64 gate-rows x 256B
            const char* srcb = (const char*)(g_lwsp[s]
                             + (size_t)(bx * 64) * KLSTM + kc * 128);
            #pragma unroll
            for (int i = 0; i < 4; i++) {
                int idx = tid + i * 256;        // 0..1023
                int r = idx >> 4, u = idx & 15;
                cpasync16(sb + s * 16384 + swz256(r, u),
                          srcb + (size_t)r * 2048 + u * 16);
            }
        }
        #pragma unroll
        for (int s = 0; s < 2; s++) {   // X: 64 batches x 256B (embedding rows)
            #pragma unroll
            for (int i = 0; i < 4; i++) {
                int idx = tid + i * 256;
                int r = idx >> 4, u = idx & 15;
                const char* src = (const char*)(g_esp[s]
                                + (size_t)toks[r] * EMBED + kc * 128);
                cpasync16(sb + 32768 + s * 16384 + swz256(r, u),
                          src + u * 16);
            }
        }
        cp_commit();
    };

    float acc[4][4];
    #pragma unroll
    for (int i = 0; i < 4; i++)
        acc[i][0] = acc[i][1] = acc[i][2] = acc[i][3] = 0.f;

    load_chunk(0, 0);

    for (int kc = 0; kc < 4; kc++) {
        if (kc < 3) load_chunk(kc + 1, (kc + 1) & 1);
        if (kc < 3) asm volatile("cp.async.wait_group 1;" ::: "memory");
        else        asm volatile("cp.async.wait_group 0;" ::: "memory");
        __syncthreads();

        const uint32_t sW = sbase + (kc & 1) * 65536;
        const uint32_t sX = sW + 32768;

        #pragma unroll
        for (int ks = 0; ks < 8; ks++) {
            uint32_t a0[4], a1[4];
            {
                int row = wm * 16 + (lane & 15);
                int u   = (ks << 1) + (lane >> 4);
                ldsm4(a0, sW + swz256(row, u));
                ldsm4(a1, sW + 16384 + swz256(row, u));
            }
            uint32_t b0[8], b1[8];
            #pragma unroll
            for (int g = 0; g < 2; g++) {
                int n = wn * 32 + g * 16 + ((lane >> 4) << 3) + (lane & 7);
                int u = (ks << 1) + ((lane >> 3) & 1);
                ldsm4(&b0[g * 4], sX + swz256(n, u));
                ldsm4(&b1[g * 4], sX + 16384 + swz256(n, u));
            }
            #pragma unroll
            for (int nt = 0; nt < 4; nt++) {
                mma16816(acc[nt], a0, &b0[nt * 2]);
                mma16816(acc[nt], a0, &b1[nt * 2]);
                mma16816(acc[nt], a1, &b0[nt * 2]);
            }
        }
        __syncthreads();
    }

    // ---- stage gates to smem transposed: Ds[b][r], pitch 68
    float* Ds = (float*)lsm;
    #pragma unroll
    for (int nt = 0; nt < 4; nt++) {
        int bb = wn * 32 + nt * 8 + ((lane & 3) << 1);
        int rr = wm * 16 + (lane >> 2);
        float* p = Ds + bb * 68 + rr;
        p[0]  = acc[nt][0];
        p[68] = acc[nt][1];
        p[8]  = acc[nt][2];
        p[76] = acc[nt][3];
    }
    __syncthreads();

    // ---- cell update: thread -> (batch b, 4 units); gates = x + gh + bias
    {
        const int b  = tid >> 2;
        const int ug = tid & 3;
        const int jb = ug * 4;                 // local units jb..jb+3
        const int ci = b * HIDDEN + bx * 16 + jb;
        const float* ghb = g_gh + (size_t)b * 2048 + bx * 64;
        float4 cold = *(const float4*)&g_c[ci];
        float co[4];
        #pragma unroll
        for (int j = 0; j < 4; j++) {
            int r = (jb + j) * 4;
            float iv = sigf (Ds[b * 68 + r + 0] + ghb[r + 0] + sbias[r + 0]);
            float fv = sigf (Ds[b * 68 + r + 1] + ghb[r + 1] + sbias[r + 1]);
            float gv = tanhf(Ds[b * 68 + r + 2] + ghb[r + 2] + sbias[r + 2]);
            float ov = sigf (Ds[b * 68 + r + 3] + ghb[r + 3] + sbias[r + 3]);
            float cprev = (j == 0) ? cold.x : (j == 1) ? cold.y
                        : (j == 2) ? cold.z : cold.w;
            float c  = fv * cprev + iv * gv;
            float hv = ov * tanhf(c);
            co[j] = c;
            __nv_bfloat16 h0, h1;
            split2(hv, h0, h1);
            g_hsp[wp_][0][ci + j] = h0;
            g_hsp[wp_][1][ci + j] = h1;
        }
        *(float4*)&g_c[ci] = make_float4(co[0], co[1], co[2], co[3]);
    }
}

// ---------------- fused fc + lstm-h kernel ---------------------------------
// grid 141 (125 fc tiles + 16 h tiles), 512 thr, one wave on 148 SMs.
// fc path (bx<125): unchanged HMMA fc, tile [256v x 64b], 8m x 2n warps.
// h path (bx>=125 or honly): Gh[128 gate-rows x 64 b] = Whh-half GEMM on
// h(phase php); K=512 in 8 chunks of 64; writes g_gh for the NEXT lstm_x.
#define FC_STAGE 81920
#define FC_SMEM  163840

__global__ void __launch_bounds__(512, 1) fc_tc_kernel(
    const float* __restrict__ fc_b, float* __restrict__ out,
    int t, int honly, int php)
{
    extern __shared__ char smem[];
    const int tid  = threadIdx.x;
    const int wid  = tid >> 5;
    const int lane = tid & 31;
    const uint32_t sbase = smem_u32(smem);

    if (!honly && blockIdx.x < 125) {
        // ================= fc path =================
        const int wm   = wid & 7;          // m block (32 rows)
        const int wn   = wid >> 3;         // n block (32 batches)
        const int v0   = blockIdx.x * 256;
        const int ph   = php;

        auto load_chunk = [&](int ck, int buf) {
            const uint32_t sb = sbase + buf * FC_STAGE;
            #pragma unroll
            for (int s = 0; s < 2; s++) {
                const char* srcb = (const char*)(g_wsp[s] + (size_t)v0 * HIDDEN + ck * 64);
                #pragma unroll
                for (int i = 0; i < 4; i++) {
                    int idx = tid + i * 512;
                    int r = idx >> 3, u = idx & 7;
                    cpasync16(sb + s * 32768 + r * 128 + ((u ^ (r & 7)) << 4),
                              srcb + (size_t)r * 1024 + u * 16);
                }
            }
            #pragma unroll
            for (int s = 0; s < 2; s++) {
                const char* srcb = (const char*)(g_hsp[ph][s] + ck * 64);
                {
                    int idx = tid;
                    int r = idx >> 3, u = idx & 7;
                    cpasync16(sb + 65536 + s * 8192 + r * 128 + ((u ^ (r & 7)) << 4),
                              srcb + (size_t)r * 1024 + u * 16);
                }
            }
            cp_commit();
        };

        float acc[8][4];   // [mt*4 + nt], mt 0..1, nt 0..3
        #pragma unroll
        for (int i = 0; i < 8; i++)
            acc[i][0] = acc[i][1] = acc[i][2] = acc[i][3] = 0.f;

        load_chunk(0, 0);

        for (int ck = 0; ck < 8; ck++) {
            if (ck < 7) load_chunk(ck + 1, (ck + 1) & 1);
            if (ck < 7) asm volatile("cp.async.wait_group 1;" ::: "memory");
            else        asm volatile("cp.async.wait_group 0;" ::: "memory");
            __syncthreads();

            const uint32_t sW = sbase + (ck & 1) * FC_STAGE;
            const uint32_t sH = sW + 65536;

            #pragma unroll
            for (int ks = 0; ks < 4; ks++) {
                uint32_t a0[8], a1[8];
                #pragma unroll
                for (int mt = 0; mt < 2; mt++) {
                    int row = wm * 32 + mt * 16 + (lane & 15);
                    int u   = (ks << 1) + (lane >> 4);
                    uint32_t addr = sW + row * 128 + ((u ^ (row & 7)) << 4);
                    ldsm4(&a0[mt * 4], addr);
                    ldsm4(&a1[mt * 4], addr + 32768);
                }
                uint32_t b0[8], b1[8];
                #pragma unroll
                for (int g = 0; g < 2; g++) {
                    int n = wn * 32 + g * 16 + ((lane >> 4) << 3) + (lane & 7);
                    int u = (ks << 1) + ((lane >> 3) & 1);
                    uint32_t addr = sH + n * 128 + ((u ^ (n & 7)) << 4);
                    ldsm4(&b0[g * 4], addr);
                    ldsm4(&b1[g * 4], addr + 8192);
                }
                #pragma unroll
                for (int mt = 0; mt < 2; mt++)
                    #pragma unroll
                    for (int nt = 0; nt < 4; nt++) {
                        mma16816(acc[mt * 4 + nt], &a0[mt * 4], &b0[nt * 2]);
                        mma16816(acc[mt * 4 + nt], &a0[mt * 4], &b1[nt * 2]);
                        mma16816(acc[mt * 4 + nt], &a1[mt * 4], &b0[nt * 2]);
                    }
            }
            __syncthreads();
        }

        float* Ds = (float*)smem;
        #pragma unroll
        for (int mt = 0; mt < 2; mt++)
            #pragma unroll
            for (int nt = 0; nt < 4; nt++) {
                int bb = wn * 32 + nt * 8 + ((lane & 3) << 1);
                int mm = wm * 32 + mt * 16 + (lane >> 2);
                float* p = Ds + bb * 260 + mm;
                p[0]   = acc[mt * 4 + nt][0];
                p[260] = acc[mt * 4 + nt][1];
                p[8]   = acc[mt * 4 + nt][2];
                p[268] = acc[mt * 4 + nt][3];
            }
        __syncthreads();

        const int b  = tid >> 3;
        const int cg = tid & 7;
        float* orow = out + (size_t)b * (TSTEPS * VOCAB) + (size_t)t * VOCAB + v0;
        float bestv = -3.4e38f;
        int   bestn = 0;
        #pragma unroll
        for (int i = 0; i < 8; i++) {
            int mm = cg * 4 + i * 32;
            float4 v  = *(const float4*)(Ds + b * 260 + mm);
            float4 bi = *(const float4*)(fc_b + v0 + mm);
            float r0 = v.x + bi.x, r1 = v.y + bi.y, r2 = v.z + bi.z, r3 = v.w + bi.w;
            *(float4*)(orow + mm) = make_float4(r0, r1, r2, r3);
            if (r0 > bestv) { bestv = r0; bestn = v0 + mm;     }
            if (r1 > bestv) { bestv = r1; bestn = v0 + mm + 1; }
            if (r2 > bestv) { bestv = r2; bestn = v0 + mm + 2; }
            if (r3 > bestv) { bestv = r3; bestn = v0 + mm + 3; }
        }
        unsigned long long key =
            ((unsigned long long)ford(bestv) << 32) | (unsigned)(~bestn);
        #pragma unroll
        for (int off = 1; off < 8; off <<= 1) {
            unsigned long long ok = __shfl_xor_sync(0xffffffffu, key, off);
            if (ok > key) key = ok;
        }
        if (cg == 0) atomicMax(&g_amax[t * BATCH + b], key);
    } else {
        // ================= lstm-h path =================
        // Gh[128 rows x 64 b] for gate-rows hx*128..+127 ; K = 512 (h half)
        const int hx = honly ? blockIdx.x : (blockIdx.x - 125);
        const int wm = wid & 7;            // 16 rows each
        const int wn = wid >> 3;           // 32 batches

        auto load_chunk_h = [&](int ck, int buf) {   // ck 0..7, 64 k each
            const uint32_t sb = sbase + buf * 49152;
            #pragma unroll
            for (int s = 0; s < 2; s++) {   // W: 128 rows x 128B
                const char* srcb = (const char*)g_lwsp[s]
                                 + (size_t)(hx * 128) * 2048 + 1024 + ck * 128;
                #pragma unroll
                for (int i = 0; i < 2; i++) {
                    int idx = tid + i * 512;       // 0..1023
                    int r = idx >> 3, u = idx & 7;
                    cpasync16(sb + s * 16384 + r * 128 + ((u ^ (r & 7)) << 4),
                              srcb + (size_t)r * 2048 + u * 16);
                }
            }
            #pragma unroll
            for (int s = 0; s < 2; s++) {   // H: 64 rows x 128B
                const char* srcb = (const char*)g_hsp[php][s] + ck * 128;
                {
                    int r = tid >> 3, u = tid & 7;
                    cpasync16(sb + 32768 + s * 8192 + r * 128 + ((u ^ (r & 7)) << 4),
                              srcb + (size_t)r * 1024 + u * 16);
                }
            }
            cp_commit();
        };

        float acc[4][4];
        #pragma unroll
        for (int i = 0; i < 4; i++)
            acc[i][0] = acc[i][1] = acc[i][2] = acc[i][3] = 0.f;

        load_chunk_h(0, 0);

        for (int ck = 0; ck < 8; ck++) {
            if (ck < 7) load_chunk_h(ck + 1, (ck + 1) & 1);
            if (ck < 7) asm volatile("cp.async.wait_group 1;" ::: "memory");
            else        asm volatile("cp.async.wait_group 0;" ::: "memory");
            __syncthreads();

            const uint32_t sW = sbase + (ck & 1) * 49152;
            const uint32_t sH = sW + 32768;

            #pragma unroll
            for (int ks = 0; ks < 4; ks++) {
                uint32_t a0[4], a1[4];
                {
                    int row = wm * 16 + (lane & 15);
                    int u   = (ks << 1) + (lane >> 4);
                    uint32_t addr = sW + row * 128 + ((u ^ (row & 7)) << 4);
                    ldsm4(a0, addr);
                    ldsm4(a1, addr + 16384);
                }
                uint32_t b0[8], b1[8];
                #pragma unroll
                for (int g = 0; g < 2; g++) {
                    int n = wn * 32 + g * 16 + ((lane >> 4) << 3) + (lane & 7);
                    int u = (ks << 1) + ((lane >> 3) & 1);
                    uint32_t addr = sH + n * 128 + ((u ^ (n & 7)) << 4);
                    ldsm4(&b0[g * 4], addr);
                    ldsm4(&b1[g * 4], addr + 8192);
                }
                #pragma unroll
                for (int nt = 0; nt < 4; nt++) {
                    mma16816(acc[nt], a0, &b0[nt * 2]);
                    mma16816(acc[nt], a0, &b1[nt * 2]);
                    mma16816(acc[nt], a1, &b0[nt * 2]);
                }
            }
            __syncthreads();
        }

        // stage transposed: Ds[b][r], pitch 132 (r local 0..127)
        float* Ds = (float*)smem;
        #pragma unroll
        for (int nt = 0; nt < 4; nt++) {
            int bb = wn * 32 + nt * 8 + ((lane & 3) << 1);
            int rr = wm * 16 + (lane >> 2);
            float* p = Ds + bb * 132 + rr;
            p[0]   = acc[nt][0];
            p[132] = acc[nt][1];
            p[8]   = acc[nt][2];
            p[140] = acc[nt][3];
        }
        __syncthreads();

        // coalesced store to g_gh[b][hx*128 + r]
        {
            const int b  = tid >> 3;
            const int rg = tid & 7;
            float* dst = g_gh + (size_t)b * 2048 + hx * 128 + rg * 16;
            const float* src = Ds + b * 132 + rg * 16;
            #pragma unroll
            for (int j = 0; j < 4; j++)
                *(float4*)(dst + j * 4) = *(const float4*)(src + j * 4);
        }
    }
}

// ---------------- launch ----------------
extern "C" void kernel_launch(void* const* d_in, const int* in_sizes, int n_in,
                              void* d_out, int out_size) {
    const float* hidden    = (const float*)d_in[0];
    const float* cell      = (const float*)d_in[1];
    /* d_in[2] = max_length (compile-time TSTEPS) */
    const int*   start_tok = (const int*)d_in[3];
    const float* embedding = (const float*)d_in[4];
    const float* w_ih      = (const float*)d_in[5];
    const float* w_hh      = (const float*)d_in[6];
    const float* b_ih      = (const float*)d_in[7];
    const float* b_hh      = (const float*)d_in[8];
    const float* fc_w      = (const float*)d_in[9];
    const float* fc_b      = (const float*)d_in[10];
    float* out = (float*)d_out;

    cudaFuncSetAttribute(fc_tc_kernel,
                         cudaFuncAttributeMaxDynamicSharedMemorySize, FC_SMEM);
    cudaFuncSetAttribute(lstm_x_kernel,
                         cudaFuncAttributeMaxDynamicSharedMemorySize, LW_SMEM);

    init_kernel<<<128, 256>>>(hidden, cell);
    split_w_kernel<<<VOCAB * HIDDEN / 1024, 256>>>(fc_w);
    split_emb_kernel<<<VOCAB * EMBED / 1024, 256>>>(embedding);
    split_lstm_w_kernel<<<4 * HIDDEN * KLSTM / 1024, 256>>>(w_ih, w_hh, b_ih, b_hh);

    // pre-compute Whh·h_init for step 0 (h-only pass, phase 0)
    fc_tc_kernel<<<16, 512, FC_SMEM>>>(fc_b, out, 0, 1, 0);

    for (int t = 0; t < TSTEPS; t++) {
        lstm_x_kernel<<<32, 256, LW_SMEM>>>(start_tok, t);
        // fc for step t + Whh·h_t for step t+1, fused in one wave
        fc_tc_kernel<<<141, 512, FC_SMEM>>>(fc_b, out, t, 0, (t & 1) ^ 1);
    }
}